// round 2
// baseline (speedup 1.0000x reference)
#include <cuda_runtime.h>
#include <math.h>

// Problem shape (fixed by the dataset)
#define BATCH 2
#define SEQ   4096
#define DIN   512
#define DOUT  512

// GEMM tiling
#define BM 128
#define BN 128
#define BK 16
#define TM 8
#define TN 8
// threads = (BM/TM)*(BN/TN) = 16*16 = 256

// Device scratch (no allocations allowed in kernel_launch)
__device__ float g_Q[BATCH * SEQ * DOUT];                    // 16 MB
__device__ float g_K[BATCH * SEQ * DOUT];                    // 16 MB
__device__ float g_V[BATCH * SEQ * DOUT];                    // 16 MB
__device__ float g_W[(long long)BATCH * SEQ * SEQ];          // 128 MB (scores/weights)

// C[M,N] = alpha * A[M,K] @ op(B)   (op = B if !TRANSB, B^T if TRANSB)
// A row-major (lda), B row-major (ldb), C row-major (ldc).
// blockIdx.z selects batch via sA/sB/sC element strides.
template <bool TRANSB>
__global__ __launch_bounds__(256) void gemm_kernel(
    const float* __restrict__ A, const float* __restrict__ B, float* __restrict__ C,
    int M, int N, int K, int lda, int ldb, int ldc,
    long long sA, long long sB, long long sC, float alpha)
{
    __shared__ float As[BK][BM];
    __shared__ float Bs[BK][BN];

    const int bz = blockIdx.z;
    A += (long long)bz * sA;
    B += (long long)bz * sB;
    C += (long long)bz * sC;

    const int tid = threadIdx.x;
    const int tx = tid & 15;   // 0..15 -> N direction
    const int ty = tid >> 4;   // 0..15 -> M direction
    const int rowBase = blockIdx.y * BM;
    const int colBase = blockIdx.x * BN;

    float acc[TM][TN];
#pragma unroll
    for (int i = 0; i < TM; i++)
#pragma unroll
        for (int j = 0; j < TN; j++) acc[i][j] = 0.0f;

    for (int k0 = 0; k0 < K; k0 += BK) {
        // ---- load A tile: BM x BK, stored transposed As[k][m] ----
#pragma unroll
        for (int l = 0; l < 2; l++) {
            int i = tid + l * 256;          // 0..511 float4 slots
            int r = i >> 2;                 // 0..127 (row within tile)
            int c = (i & 3) * 4;            // 0,4,8,12 (k within tile)
            float4 v = *reinterpret_cast<const float4*>(
                &A[(long long)(rowBase + r) * lda + (k0 + c)]);
            As[c + 0][r] = v.x;
            As[c + 1][r] = v.y;
            As[c + 2][r] = v.z;
            As[c + 3][r] = v.w;
        }
        // ---- load B tile ----
        if (TRANSB) {
            // B is [N, K] row-major; tile rows are n, cols are k
#pragma unroll
            for (int l = 0; l < 2; l++) {
                int i = tid + l * 256;
                int r = i >> 2;             // n within tile (0..127)
                int c = (i & 3) * 4;        // k within tile
                float4 v = *reinterpret_cast<const float4*>(
                    &B[(long long)(colBase + r) * ldb + (k0 + c)]);
                Bs[c + 0][r] = v.x;
                Bs[c + 1][r] = v.y;
                Bs[c + 2][r] = v.z;
                Bs[c + 3][r] = v.w;
            }
        } else {
            // B is [K, N] row-major; tile rows are k, cols are n
#pragma unroll
            for (int l = 0; l < 2; l++) {
                int i = tid + l * 256;
                int r = i >> 5;             // k within tile (0..15)
                int c = (i & 31) * 4;       // n within tile (0..124)
                float4 v = *reinterpret_cast<const float4*>(
                    &B[(long long)(k0 + r) * ldb + (colBase + c)]);
                *reinterpret_cast<float4*>(&Bs[r][c]) = v;
            }
        }
        __syncthreads();

        // ---- compute ----
#pragma unroll
        for (int k = 0; k < BK; k++) {
            float ra[TM], rb[TN];
#pragma unroll
            for (int i = 0; i < TM; i++) ra[i] = As[k][ty * TM + i];
#pragma unroll
            for (int j = 0; j < TN; j++) rb[j] = Bs[k][tx * TN + j];
#pragma unroll
            for (int i = 0; i < TM; i++)
#pragma unroll
                for (int j = 0; j < TN; j++)
                    acc[i][j] = fmaf(ra[i], rb[j], acc[i][j]);
        }
        __syncthreads();
    }

    // ---- epilogue ----
#pragma unroll
    for (int i = 0; i < TM; i++) {
        int r = rowBase + ty * TM + i;
#pragma unroll
        for (int j = 0; j < TN; j += 4) {
            float4 v = make_float4(acc[i][j + 0] * alpha,
                                   acc[i][j + 1] * alpha,
                                   acc[i][j + 2] * alpha,
                                   acc[i][j + 3] * alpha);
            *reinterpret_cast<float4*>(
                &C[(long long)r * ldc + colBase + tx * TN + j]) = v;
        }
    }
}

// Row softmax in-place over rows of length S. One CTA per row.
__global__ __launch_bounds__(256) void softmax_kernel(float* __restrict__ A, int S)
{
    long long row = blockIdx.x;
    float* p = A + row * (long long)S;
    const int tid = threadIdx.x;
    __shared__ float red[256];

    // pass 1: max
    float m = -1e30f;
    for (int i = tid; i < S; i += 256) m = fmaxf(m, p[i]);
    red[tid] = m;
    __syncthreads();
    for (int s = 128; s > 0; s >>= 1) {
        if (tid < s) red[tid] = fmaxf(red[tid], red[tid + s]);
        __syncthreads();
    }
    m = red[0];
    __syncthreads();

    // pass 2: exp + sum
    float sum = 0.0f;
    for (int i = tid; i < S; i += 256) {
        float e = __expf(p[i] - m);
        p[i] = e;
        sum += e;
    }
    red[tid] = sum;
    __syncthreads();
    for (int s = 128; s > 0; s >>= 1) {
        if (tid < s) red[tid] += red[tid + s];
        __syncthreads();
    }
    float inv = 1.0f / red[0];
    __syncthreads();

    // pass 3: normalize
    for (int i = tid; i < S; i += 256) p[i] *= inv;
}

extern "C" void kernel_launch(void* const* d_in, const int* in_sizes, int n_in,
                              void* d_out, int out_size)
{
    const float* x  = (const float*)d_in[0];   // [B, S, DIN]
    const float* Wq = (const float*)d_in[1];   // [DIN, DOUT]
    const float* Wk = (const float*)d_in[2];
    const float* Wv = (const float*)d_in[3];
    float* out = (float*)d_out;                // [B, S, DOUT]

    float *Q, *K, *V, *W;
    cudaGetSymbolAddress((void**)&Q, g_Q);
    cudaGetSymbolAddress((void**)&K, g_K);
    cudaGetSymbolAddress((void**)&V, g_V);
    cudaGetSymbolAddress((void**)&W, g_W);

    const int M_proj = BATCH * SEQ;            // 8192

    // 1) QKV projections: [8192,512] = [8192,512] @ [512,512]
    {
        dim3 grid(DOUT / BN, M_proj / BM, 1);  // (4, 64)
        gemm_kernel<false><<<grid, 256>>>(x, Wq, Q, M_proj, DOUT, DIN,
                                          DIN, DOUT, DOUT, 0, 0, 0, 1.0f);
        gemm_kernel<false><<<grid, 256>>>(x, Wk, K, M_proj, DOUT, DIN,
                                          DIN, DOUT, DOUT, 0, 0, 0, 1.0f);
        gemm_kernel<false><<<grid, 256>>>(x, Wv, V, M_proj, DOUT, DIN,
                                          DIN, DOUT, DOUT, 0, 0, 0, 1.0f);
    }

    // 2) scores = (Q @ K^T) / sqrt(DOUT), per batch: [4096,4096]
    {
        dim3 grid(SEQ / BN, SEQ / BM, BATCH);  // (32, 32, 2)
        const float scale = 0.044194173824159216f;  // 1/sqrt(512)
        gemm_kernel<true><<<grid, 256>>>(Q, K, W, SEQ, SEQ, DOUT,
                                         DOUT, DOUT, SEQ,
                                         (long long)SEQ * DOUT,
                                         (long long)SEQ * DOUT,
                                         (long long)SEQ * SEQ, scale);
    }

    // 3) row softmax over 8192 rows of length 4096
    softmax_kernel<<<BATCH * SEQ, 256>>>(W, SEQ);

    // 4) context = weights @ V, per batch: [4096,512] = [4096,4096] @ [4096,512]
    {
        dim3 grid(DOUT / BN, SEQ / BM, BATCH); // (4, 32, 2)
        gemm_kernel<false><<<grid, 256>>>(W, V, out, SEQ, DOUT, SEQ,
                                          SEQ, DOUT, DOUT,
                                          (long long)SEQ * SEQ,
                                          (long long)SEQ * DOUT,
                                          (long long)SEQ * DOUT, 1.0f);
    }
}

// round 4
// speedup vs baseline: 2.1654x; 2.1654x over previous
#include <cuda_runtime.h>
#include <cuda_bf16.h>
#include <cstdint>
#include <math.h>

#define BATCH 2
#define SEQ   4096
#define DM    512
#define MTOT  (BATCH*SEQ)            // 8192

// ---------------- device scratch (no allocs allowed) ----------------
__device__ __nv_bfloat16 g_xh[MTOT*DM], g_xl[MTOT*DM];                 // x split
__device__ __nv_bfloat16 g_Wqth[DM*DM], g_Wqtl[DM*DM];                 // W^T split
__device__ __nv_bfloat16 g_Wkth[DM*DM], g_Wktl[DM*DM];
__device__ __nv_bfloat16 g_Wvth[DM*DM], g_Wvtl[DM*DM];
__device__ __nv_bfloat16 g_Qh[MTOT*DM], g_Ql[MTOT*DM];
__device__ __nv_bfloat16 g_Kh[MTOT*DM], g_Kl[MTOT*DM];
__device__ __nv_bfloat16 g_Vth[DM*MTOT], g_Vtl[DM*MTOT];               // V^T [512, 8192]
__device__ float         g_S[(long long)BATCH*SEQ*SEQ];                // scores fp32
__device__ __nv_bfloat16 g_Ph[(long long)BATCH*SEQ*SEQ];               // softmax split
__device__ __nv_bfloat16 g_Pl[(long long)BATCH*SEQ*SEQ];

// ---------------- PTX helpers ----------------
__device__ __forceinline__ uint32_t smem_u32(const void* p) {
    uint32_t a;
    asm("{ .reg .u64 t; cvta.to.shared.u64 t, %1; cvt.u32.u64 %0, t; }" : "=r"(a) : "l"(p));
    return a;
}
__device__ __forceinline__ void cpasync16(uint32_t dst, const void* src) {
    asm volatile("cp.async.cg.shared.global [%0], [%1], 16;" :: "r"(dst), "l"(src));
}
__device__ __forceinline__ void cp_commit() {
    asm volatile("cp.async.commit_group;" ::: "memory");
}
template<int N>
__device__ __forceinline__ void cp_wait() {
    asm volatile("cp.async.wait_group %0;" :: "n"(N) : "memory");
}
__device__ __forceinline__ uint32_t lds32(uint32_t a) {
    uint32_t v;
    asm volatile("ld.shared.b32 %0, [%1];" : "=r"(v) : "r"(a));
    return v;
}
__device__ __forceinline__ void mma16816(float* c, const uint32_t* a, const uint32_t* b) {
    asm volatile(
        "mma.sync.aligned.m16n8k16.row.col.f32.bf16.bf16.f32 "
        "{%0,%1,%2,%3}, {%4,%5,%6,%7}, {%8,%9}, {%0,%1,%2,%3};"
        : "+f"(c[0]), "+f"(c[1]), "+f"(c[2]), "+f"(c[3])
        : "r"(a[0]), "r"(a[1]), "r"(a[2]), "r"(a[3]), "r"(b[0]), "r"(b[1]));
}

// ---------------- HMMA split-bf16 GEMM ----------------
// C[M,N] = alpha * A @ B^T  with A[M,K] (h/l), B[N,K] (h/l) row-major bf16.
// 128x128 CTA tile, BK=32, double-buffered cp.async, 8 warps (2Mx4N), warp tile 64x32.
// EPI==0: fp32 C.  EPI==1: bf16 split (Ch, Cl).
#define ROWB   80                  // padded row stride in bytes (40 bf16)
#define MAT_B  (128*ROWB)          // 10240 B per matrix tile
#define STAGE_B (4*MAT_B)          // 40960 B per stage
#define GSMEM  (2*STAGE_B + 128)   // ~80 KB

template<int EPI>
__global__ __launch_bounds__(256) void mma_gemm(
    const __nv_bfloat16* __restrict__ Ah, const __nv_bfloat16* __restrict__ Al,
    const __nv_bfloat16* __restrict__ Bh, const __nv_bfloat16* __restrict__ Bl,
    float* __restrict__ C, __nv_bfloat16* __restrict__ Ch, __nv_bfloat16* __restrict__ Cl,
    int K, int lda, int ldb, int ldc,
    long long sA, long long sB, long long sC, float alpha)
{
    extern __shared__ char dsm[];
    const uint32_t smem0 = (smem_u32(dsm) + 127) & ~127u;

    const int tid = threadIdx.x;
    const int lane = tid & 31;
    const int wid = tid >> 5;
    const int warpM = wid & 1;      // 0..1
    const int warpN = wid >> 1;     // 0..3
    const int g = lane >> 2;        // 0..7
    const int tig = lane & 3;       // 0..3

    const long long bz = blockIdx.z;
    Ah += bz * sA; Al += bz * sA;
    Bh += bz * sB; Bl += bz * sB;
    const int rowBase = blockIdx.y * 128;
    const int colBase = blockIdx.x * 128;

    // per-thread load geometry: q = seg (16B), rbase = row slot
    const int q = tid & 3;
    const int rbase = tid >> 2;     // 0..63

    const __nv_bfloat16* srcA_h = Ah + (long long)rowBase * lda + q * 8;
    const __nv_bfloat16* srcA_l = Al + (long long)rowBase * lda + q * 8;
    const __nv_bfloat16* srcB_h = Bh + (long long)colBase * ldb + q * 8;
    const __nv_bfloat16* srcB_l = Bl + (long long)colBase * ldb + q * 8;

    auto load_stage = [&](int buf, int k0) {
        const uint32_t stg = smem0 + buf * STAGE_B;
#pragma unroll
        for (int i = 0; i < 8; i++) {
            const int mat = i >> 1;                 // compile-time per unrolled i
            const int r = rbase + (i & 1) * 64;     // 0..127
            const uint32_t dst = stg + mat * MAT_B + r * ROWB + q * 16;
            const __nv_bfloat16* src;
            if (mat == 0)      src = srcA_h + (long long)r * lda + k0;
            else if (mat == 1) src = srcA_l + (long long)r * lda + k0;
            else if (mat == 2) src = srcB_h + (long long)r * ldb + k0;
            else               src = srcB_l + (long long)r * ldb + k0;
            cpasync16(dst, src);
        }
        cp_commit();
    };

    float acc[4][4][4];
#pragma unroll
    for (int mt = 0; mt < 4; mt++)
#pragma unroll
        for (int nt = 0; nt < 4; nt++)
#pragma unroll
            for (int v = 0; v < 4; v++) acc[mt][nt][v] = 0.0f;

    const int NC = K >> 5;
    load_stage(0, 0);

    for (int it = 0; it < NC; it++) {
        if (it + 1 < NC) {
            load_stage((it + 1) & 1, (it + 1) << 5);
            cp_wait<1>();
        } else {
            cp_wait<0>();
        }
        __syncthreads();

        const uint32_t stg = smem0 + (it & 1) * STAGE_B;
        const uint32_t sAh = stg;
        const uint32_t sAl = stg + MAT_B;
        const uint32_t sBh = stg + 2 * MAT_B;
        const uint32_t sBl = stg + 3 * MAT_B;

#pragma unroll
        for (int ks = 0; ks < 2; ks++) {
            const uint32_t cb0 = (ks * 16 + tig * 2) * 2;   // byte col offset
            const uint32_t cb1 = cb0 + 16;                  // +8 cols

            uint32_t ah[4][4], al[4][4], bh[4][2], bl[4][2];
#pragma unroll
            for (int mt = 0; mt < 4; mt++) {
                const uint32_t r0 = (uint32_t)(warpM * 64 + mt * 16 + g) * ROWB;
                const uint32_t r1 = r0 + 8 * ROWB;
                ah[mt][0] = lds32(sAh + r0 + cb0);
                ah[mt][1] = lds32(sAh + r1 + cb0);
                ah[mt][2] = lds32(sAh + r0 + cb1);
                ah[mt][3] = lds32(sAh + r1 + cb1);
                al[mt][0] = lds32(sAl + r0 + cb0);
                al[mt][1] = lds32(sAl + r1 + cb0);
                al[mt][2] = lds32(sAl + r0 + cb1);
                al[mt][3] = lds32(sAl + r1 + cb1);
            }
#pragma unroll
            for (int nt = 0; nt < 4; nt++) {
                const uint32_t rb = (uint32_t)(warpN * 32 + nt * 8 + g) * ROWB;
                bh[nt][0] = lds32(sBh + rb + cb0);
                bh[nt][1] = lds32(sBh + rb + cb1);
                bl[nt][0] = lds32(sBl + rb + cb0);
                bl[nt][1] = lds32(sBl + rb + cb1);
            }
#pragma unroll
            for (int mt = 0; mt < 4; mt++)
#pragma unroll
                for (int nt = 0; nt < 4; nt++) {
                    mma16816(acc[mt][nt], ah[mt], bh[nt]);
                    mma16816(acc[mt][nt], ah[mt], bl[nt]);
                    mma16816(acc[mt][nt], al[mt], bh[nt]);
                }
        }
        __syncthreads();
    }

    // ---- epilogue ----
#pragma unroll
    for (int mt = 0; mt < 4; mt++) {
#pragma unroll
        for (int nt = 0; nt < 4; nt++) {
            const int row = rowBase + warpM * 64 + mt * 16 + g;
            const int col = colBase + warpN * 32 + nt * 8 + tig * 2;
            if (EPI == 0) {
                float2 v0 = make_float2(acc[mt][nt][0] * alpha, acc[mt][nt][1] * alpha);
                float2 v1 = make_float2(acc[mt][nt][2] * alpha, acc[mt][nt][3] * alpha);
                float* base = C + bz * sC;
                *(float2*)(base + (long long)row * ldc + col) = v0;
                *(float2*)(base + (long long)(row + 8) * ldc + col) = v1;
            } else {
                long long o0 = (long long)row * ldc + col;
                long long o1 = (long long)(row + 8) * ldc + col;
#pragma unroll
                for (int hv = 0; hv < 2; hv++) {
                    float v0 = acc[mt][nt][hv * 2 + 0];
                    float v1 = acc[mt][nt][hv * 2 + 1];
                    __nv_bfloat16 h0 = __float2bfloat16(v0);
                    __nv_bfloat16 h1 = __float2bfloat16(v1);
                    __nv_bfloat162 hh; hh.x = h0; hh.y = h1;
                    __nv_bfloat162 ll;
                    ll.x = __float2bfloat16(v0 - __bfloat162float(h0));
                    ll.y = __float2bfloat16(v1 - __bfloat162float(h1));
                    long long o = hv ? o1 : o0;
                    *(__nv_bfloat162*)(Ch + o) = hh;
                    *(__nv_bfloat162*)(Cl + o) = ll;
                }
            }
        }
    }
}

// ---------------- elementwise split-convert (x) ----------------
__global__ __launch_bounds__(256) void convert_split(
    const float* __restrict__ x, __nv_bfloat16* __restrict__ h,
    __nv_bfloat16* __restrict__ l, int n4)
{
    int i = blockIdx.x * 256 + threadIdx.x;
    if (i >= n4) return;
    float4 v = ((const float4*)x)[i];
    __nv_bfloat16 h0 = __float2bfloat16(v.x), h1 = __float2bfloat16(v.y);
    __nv_bfloat16 h2 = __float2bfloat16(v.z), h3 = __float2bfloat16(v.w);
    __nv_bfloat162 ha; ha.x = h0; ha.y = h1;
    __nv_bfloat162 hb; hb.x = h2; hb.y = h3;
    __nv_bfloat162 la; la.x = __float2bfloat16(v.x - __bfloat162float(h0));
    la.y = __float2bfloat16(v.y - __bfloat162float(h1));
    __nv_bfloat162 lb; lb.x = __float2bfloat16(v.z - __bfloat162float(h2));
    lb.y = __float2bfloat16(v.w - __bfloat162float(h3));
    ((__nv_bfloat162*)h)[2*i]   = ha;
    ((__nv_bfloat162*)h)[2*i+1] = hb;
    ((__nv_bfloat162*)l)[2*i]   = la;
    ((__nv_bfloat162*)l)[2*i+1] = lb;
}

// ---------------- transpose + split-convert (W -> W^T) ----------------
__global__ __launch_bounds__(256) void wtrans_split(
    const float* __restrict__ W, __nv_bfloat16* __restrict__ th,
    __nv_bfloat16* __restrict__ tl)
{
    int idx = blockIdx.x * 256 + threadIdx.x;   // over 512*512
    int k = idx >> 9, n = idx & 511;
    float v = W[idx];                            // W[k][n], coalesced read
    __nv_bfloat16 h = __float2bfloat16(v);
    __nv_bfloat16 l = __float2bfloat16(v - __bfloat162float(h));
    th[n * 512 + k] = h;
    tl[n * 512 + k] = l;
}

// ---------------- softmax with fused bf16 split ----------------
__global__ __launch_bounds__(256) void softmax_split(
    const float* __restrict__ S, __nv_bfloat16* __restrict__ Ph,
    __nv_bfloat16* __restrict__ Pl)
{
    long long row = blockIdx.x;
    const float4* p = (const float4*)(S + row * SEQ);
    const int tid = threadIdx.x;
    const int wid = tid >> 5, lane = tid & 31;
    __shared__ float red[8];

    float4 v[4];
#pragma unroll
    for (int j = 0; j < 4; j++) v[j] = p[tid + j * 256];

    float m = -1e30f;
#pragma unroll
    for (int j = 0; j < 4; j++)
        m = fmaxf(m, fmaxf(fmaxf(v[j].x, v[j].y), fmaxf(v[j].z, v[j].w)));
#pragma unroll
    for (int o = 16; o > 0; o >>= 1) m = fmaxf(m, __shfl_xor_sync(0xFFFFFFFF, m, o));
    if (lane == 0) red[wid] = m;
    __syncthreads();
    m = red[0];
#pragma unroll
    for (int w = 1; w < 8; w++) m = fmaxf(m, red[w]);
    __syncthreads();

    float sum = 0.0f;
#pragma unroll
    for (int j = 0; j < 4; j++) {
        v[j].x = __expf(v[j].x - m); v[j].y = __expf(v[j].y - m);
        v[j].z = __expf(v[j].z - m); v[j].w = __expf(v[j].w - m);
        sum += v[j].x + v[j].y + v[j].z + v[j].w;
    }
#pragma unroll
    for (int o = 16; o > 0; o >>= 1) sum += __shfl_xor_sync(0xFFFFFFFF, sum, o);
    if (lane == 0) red[wid] = sum;
    __syncthreads();
    sum = 0.0f;
#pragma unroll
    for (int w = 0; w < 8; w++) sum += red[w];
    float inv = 1.0f / sum;

    __nv_bfloat162* dh = (__nv_bfloat162*)(Ph + row * SEQ);
    __nv_bfloat162* dl = (__nv_bfloat162*)(Pl + row * SEQ);
#pragma unroll
    for (int j = 0; j < 4; j++) {
        int e = (tid + j * 256) * 2;   // bf162 index
        float a = v[j].x * inv, b = v[j].y * inv, c = v[j].z * inv, d2 = v[j].w * inv;
        __nv_bfloat16 ha = __float2bfloat16(a), hb = __float2bfloat16(b);
        __nv_bfloat16 hc = __float2bfloat16(c), hd = __float2bfloat16(d2);
        __nv_bfloat162 p0; p0.x = ha; p0.y = hb;
        __nv_bfloat162 p1; p1.x = hc; p1.y = hd;
        __nv_bfloat162 q0; q0.x = __float2bfloat16(a - __bfloat162float(ha));
        q0.y = __float2bfloat16(b - __bfloat162float(hb));
        __nv_bfloat162 q1; q1.x = __float2bfloat16(c - __bfloat162float(hc));
        q1.y = __float2bfloat16(d2 - __bfloat162float(hd));
        dh[e] = p0; dh[e + 1] = p1;
        dl[e] = q0; dl[e + 1] = q1;
    }
}

// ---------------- host ----------------
extern "C" void kernel_launch(void* const* d_in, const int* in_sizes, int n_in,
                              void* d_out, int out_size)
{
    const float* x  = (const float*)d_in[0];
    const float* Wq = (const float*)d_in[1];
    const float* Wk = (const float*)d_in[2];
    const float* Wv = (const float*)d_in[3];
    float* out = (float*)d_out;

    __nv_bfloat16 *xh, *xl, *Wqth, *Wqtl, *Wkth, *Wktl, *Wvth, *Wvtl;
    __nv_bfloat16 *Qh, *Ql, *Kh, *Kl, *Vth, *Vtl, *Ph, *Pl;
    float* S;
    cudaGetSymbolAddress((void**)&xh, g_xh);   cudaGetSymbolAddress((void**)&xl, g_xl);
    cudaGetSymbolAddress((void**)&Wqth, g_Wqth); cudaGetSymbolAddress((void**)&Wqtl, g_Wqtl);
    cudaGetSymbolAddress((void**)&Wkth, g_Wkth); cudaGetSymbolAddress((void**)&Wktl, g_Wktl);
    cudaGetSymbolAddress((void**)&Wvth, g_Wvth); cudaGetSymbolAddress((void**)&Wvtl, g_Wvtl);
    cudaGetSymbolAddress((void**)&Qh, g_Qh);   cudaGetSymbolAddress((void**)&Ql, g_Ql);
    cudaGetSymbolAddress((void**)&Kh, g_Kh);   cudaGetSymbolAddress((void**)&Kl, g_Kl);
    cudaGetSymbolAddress((void**)&Vth, g_Vth); cudaGetSymbolAddress((void**)&Vtl, g_Vtl);
    cudaGetSymbolAddress((void**)&Ph, g_Ph);   cudaGetSymbolAddress((void**)&Pl, g_Pl);
    cudaGetSymbolAddress((void**)&S, g_S);

    cudaFuncSetAttribute(mma_gemm<0>, cudaFuncAttributeMaxDynamicSharedMemorySize, GSMEM);
    cudaFuncSetAttribute(mma_gemm<1>, cudaFuncAttributeMaxDynamicSharedMemorySize, GSMEM);

    // 1) split-convert x; transpose-split W
    convert_split<<<(MTOT*DM/4 + 255)/256, 256>>>(x, xh, xl, MTOT*DM/4);
    wtrans_split<<<DM*DM/256, 256>>>(Wq, Wqth, Wqtl);
    wtrans_split<<<DM*DM/256, 256>>>(Wk, Wkth, Wktl);
    wtrans_split<<<DM*DM/256, 256>>>(Wv, Wvth, Wvtl);

    // 2) Q = x@Wq, K = x@Wk  (split epilogue)
    {
        dim3 g(DM/128, MTOT/128, 1);
        mma_gemm<1><<<g, 256, GSMEM>>>(xh, xl, Wqth, Wqtl, nullptr, Qh, Ql,
                                       DM, DM, DM, DM, 0, 0, 0, 1.0f);
        mma_gemm<1><<<g, 256, GSMEM>>>(xh, xl, Wkth, Wktl, nullptr, Kh, Kl,
                                       DM, DM, DM, DM, 0, 0, 0, 1.0f);
    }
    // 3) V^T = Wv^T @ x^T : A=Wvt [512,512], B=x [8192,512] -> C [512, 8192]
    {
        dim3 g(MTOT/128, DM/128, 1);
        mma_gemm<1><<<g, 256, GSMEM>>>(Wvth, Wvtl, xh, xl, nullptr, Vth, Vtl,
                                       DM, DM, DM, MTOT, 0, 0, 0, 1.0f);
    }
    // 4) scores = (Q @ K^T) / sqrt(512)  (fp32 epilogue)
    {
        dim3 g(SEQ/128, SEQ/128, BATCH);
        mma_gemm<0><<<g, 256, GSMEM>>>(Qh, Ql, Kh, Kl, S, nullptr, nullptr,
                                       DM, DM, DM, SEQ,
                                       (long long)SEQ*DM, (long long)SEQ*DM,
                                       (long long)SEQ*SEQ, 0.044194173824159216f);
    }
    // 5) softmax + split
    softmax_split<<<BATCH*SEQ, 256>>>(S, Ph, Pl);

    // 6) out = P @ V = P @ (V^T)^T : A=P[4096,4096(k)], B=Vt rows are n, k along 8192 cols
    {
        dim3 g(DM/128, SEQ/128, BATCH);
        mma_gemm<0><<<g, 256, GSMEM>>>(Ph, Pl, Vth, Vtl, out, nullptr, nullptr,
                                       SEQ, SEQ, MTOT, DM,
                                       (long long)SEQ*SEQ, (long long)SEQ,
                                       (long long)SEQ*DM, 1.0f);
    }
}

// round 5
// speedup vs baseline: 2.2745x; 1.0504x over previous
#include <cuda_runtime.h>
#include <cuda_bf16.h>
#include <cstdint>
#include <math.h>

#define BATCH 2
#define SEQ   4096
#define DM    512
#define MTOT  (BATCH*SEQ)            // 8192

// ---------------- device scratch (no allocs allowed) ----------------
__device__ __nv_bfloat16 g_xh[MTOT*DM], g_xl[MTOT*DM];                 // x split
__device__ __nv_bfloat16 g_Wqth[DM*DM], g_Wqtl[DM*DM];                 // W^T split
__device__ __nv_bfloat16 g_Wkth[DM*DM], g_Wktl[DM*DM];
__device__ __nv_bfloat16 g_Wvth[DM*DM], g_Wvtl[DM*DM];
__device__ __nv_bfloat16 g_Qh[MTOT*DM], g_Ql[MTOT*DM];
__device__ __nv_bfloat16 g_Kh[MTOT*DM], g_Kl[MTOT*DM];
__device__ __nv_bfloat16 g_Vth[DM*MTOT], g_Vtl[DM*MTOT];               // V^T [512, 8192]
__device__ float         g_S[(long long)BATCH*SEQ*SEQ];                // scores fp32
__device__ __nv_bfloat16 g_Ph[(long long)BATCH*SEQ*SEQ];               // softmax split
__device__ __nv_bfloat16 g_Pl[(long long)BATCH*SEQ*SEQ];

// ---------------- PTX helpers ----------------
__device__ __forceinline__ uint32_t smem_u32(const void* p) {
    uint32_t a;
    asm("{ .reg .u64 t; cvta.to.shared.u64 t, %1; cvt.u32.u64 %0, t; }" : "=r"(a) : "l"(p));
    return a;
}
__device__ __forceinline__ void cpasync16(uint32_t dst, const void* src) {
    asm volatile("cp.async.cg.shared.global [%0], [%1], 16;" :: "r"(dst), "l"(src));
}
__device__ __forceinline__ void cp_commit() {
    asm volatile("cp.async.commit_group;" ::: "memory");
}
template<int N>
__device__ __forceinline__ void cp_wait() {
    asm volatile("cp.async.wait_group %0;" :: "n"(N) : "memory");
}
__device__ __forceinline__ void ldmx4(uint32_t* r, uint32_t addr) {
    asm volatile("ldmatrix.sync.aligned.m8n8.x4.shared.b16 {%0,%1,%2,%3}, [%4];"
                 : "=r"(r[0]), "=r"(r[1]), "=r"(r[2]), "=r"(r[3]) : "r"(addr));
}
__device__ __forceinline__ void mma16816(float* c, const uint32_t* a, const uint32_t* b) {
    asm volatile(
        "mma.sync.aligned.m16n8k16.row.col.f32.bf16.bf16.f32 "
        "{%0,%1,%2,%3}, {%4,%5,%6,%7}, {%8,%9}, {%0,%1,%2,%3};"
        : "+f"(c[0]), "+f"(c[1]), "+f"(c[2]), "+f"(c[3])
        : "r"(a[0]), "r"(a[1]), "r"(a[2]), "r"(a[3]), "r"(b[0]), "r"(b[1]));
}

// ---------------- HMMA split-bf16 GEMM ----------------
// C[M,N] = alpha * A @ B^T  with A[M,K] (h/l), B[N,K] (h/l) row-major bf16.
// 128x128 CTA tile, BK=32, 3-stage cp.async pipeline, 8 warps (2Mx4N), warp 64x32.
// Fragment loads via ldmatrix.x4 (conflict-free with 80B row padding: 5i mod 8).
// EPI==0: fp32 C.  EPI==1: bf16 split (Ch, Cl).
#define ROWB    80                 // padded row stride in bytes (40 bf16)
#define MAT_B   (128*ROWB)         // 10240 B per matrix tile
#define STAGE_B (4*MAT_B)          // 40960 B per stage
#define NSTAGE  3
#define GSMEM   (NSTAGE*STAGE_B + 128)

template<int EPI>
__global__ __launch_bounds__(256, 1) void mma_gemm(
    const __nv_bfloat16* __restrict__ Ah, const __nv_bfloat16* __restrict__ Al,
    const __nv_bfloat16* __restrict__ Bh, const __nv_bfloat16* __restrict__ Bl,
    float* __restrict__ C, __nv_bfloat16* __restrict__ Ch, __nv_bfloat16* __restrict__ Cl,
    int K, int lda, int ldb, int ldc,
    long long sA, long long sB, long long sC, float alpha)
{
    extern __shared__ char dsm[];
    const uint32_t smem0 = (smem_u32(dsm) + 127) & ~127u;

    const int tid = threadIdx.x;
    const int lane = tid & 31;
    const int wid = tid >> 5;
    const int warpM = wid & 1;      // 0..1
    const int warpN = wid >> 1;     // 0..3
    const int g = lane >> 2;        // 0..7
    const int tig = lane & 3;       // 0..3

    const long long bz = blockIdx.z;
    Ah += bz * sA; Al += bz * sA;
    Bh += bz * sB; Bl += bz * sB;
    const int rowBase = blockIdx.y * 128;
    const int colBase = blockIdx.x * 128;

    // ---- cp.async load geometry ----
    const int q = tid & 3;          // 16B segment within 64B row
    const int rbase = tid >> 2;     // 0..63

    const __nv_bfloat16* srcA_h = Ah + (long long)rowBase * lda + q * 8;
    const __nv_bfloat16* srcA_l = Al + (long long)rowBase * lda + q * 8;
    const __nv_bfloat16* srcB_h = Bh + (long long)colBase * ldb + q * 8;
    const __nv_bfloat16* srcB_l = Bl + (long long)colBase * ldb + q * 8;

    auto load_stage = [&](int buf, int k0) {
        const uint32_t stg = smem0 + buf * STAGE_B;
#pragma unroll
        for (int i = 0; i < 8; i++) {
            const int mat = i >> 1;
            const int r = rbase + (i & 1) * 64;
            const uint32_t dst = stg + mat * MAT_B + r * ROWB + q * 16;
            const __nv_bfloat16* src;
            if (mat == 0)      src = srcA_h + (long long)r * lda + k0;
            else if (mat == 1) src = srcA_l + (long long)r * lda + k0;
            else if (mat == 2) src = srcB_h + (long long)r * ldb + k0;
            else               src = srcB_l + (long long)r * ldb + k0;
            cpasync16(dst, src);
        }
        cp_commit();
    };

    // ---- ldmatrix per-lane address offsets ----
    const int tile = lane >> 3, trow = lane & 7;
    const uint32_t aoff = (uint32_t)((warpM * 64 + ((tile & 1) << 3) + trow) * ROWB
                                     + ((tile >> 1) << 4));
    const uint32_t boff = (uint32_t)((warpN * 32 + ((tile >> 1) << 3) + trow) * ROWB
                                     + ((tile & 1) << 4));

    float acc[4][4][4];
#pragma unroll
    for (int mt = 0; mt < 4; mt++)
#pragma unroll
        for (int nt = 0; nt < 4; nt++)
#pragma unroll
            for (int v = 0; v < 4; v++) acc[mt][nt][v] = 0.0f;

    const int NC = K >> 5;
    load_stage(0, 0);
    if (NC > 1) load_stage(1, 32);

    for (int it = 0; it < NC; it++) {
        if (it + 2 < NC) { load_stage((it + 2) % NSTAGE, (it + 2) << 5); cp_wait<2>(); }
        else if (it + 1 < NC) { cp_wait<1>(); }
        else { cp_wait<0>(); }
        __syncthreads();

        const uint32_t stg = smem0 + (it % NSTAGE) * STAGE_B;
        const uint32_t sAh = stg;
        const uint32_t sAl = stg + MAT_B;
        const uint32_t sBh = stg + 2 * MAT_B;
        const uint32_t sBl = stg + 3 * MAT_B;

#pragma unroll
        for (int ks = 0; ks < 2; ks++) {
            const uint32_t kb = ks * 32;   // 16 cols * 2B

            uint32_t ah[4][4], al[4][4], bh[4][2], bl[4][2];
#pragma unroll
            for (int mt = 0; mt < 4; mt++) {
                ldmx4(ah[mt], sAh + aoff + mt * (16 * ROWB) + kb);
                ldmx4(al[mt], sAl + aoff + mt * (16 * ROWB) + kb);
            }
#pragma unroll
            for (int p = 0; p < 2; p++) {
                ldmx4(&bh[2 * p][0], sBh + boff + p * (16 * ROWB) + kb);
                ldmx4(&bl[2 * p][0], sBl + boff + p * (16 * ROWB) + kb);
            }
#pragma unroll
            for (int mt = 0; mt < 4; mt++)
#pragma unroll
                for (int nt = 0; nt < 4; nt++) {
                    mma16816(acc[mt][nt], ah[mt], bh[nt]);
                    mma16816(acc[mt][nt], ah[mt], bl[nt]);
                    mma16816(acc[mt][nt], al[mt], bh[nt]);
                }
        }
        __syncthreads();
    }

    // ---- epilogue ----
#pragma unroll
    for (int mt = 0; mt < 4; mt++) {
#pragma unroll
        for (int nt = 0; nt < 4; nt++) {
            const int row = rowBase + warpM * 64 + mt * 16 + g;
            const int col = colBase + warpN * 32 + nt * 8 + tig * 2;
            if (EPI == 0) {
                float2 v0 = make_float2(acc[mt][nt][0] * alpha, acc[mt][nt][1] * alpha);
                float2 v1 = make_float2(acc[mt][nt][2] * alpha, acc[mt][nt][3] * alpha);
                float* base = C + bz * sC;
                *(float2*)(base + (long long)row * ldc + col) = v0;
                *(float2*)(base + (long long)(row + 8) * ldc + col) = v1;
            } else {
                long long o0 = (long long)row * ldc + col;
                long long o1 = (long long)(row + 8) * ldc + col;
#pragma unroll
                for (int hv = 0; hv < 2; hv++) {
                    float v0 = acc[mt][nt][hv * 2 + 0];
                    float v1 = acc[mt][nt][hv * 2 + 1];
                    __nv_bfloat16 h0 = __float2bfloat16(v0);
                    __nv_bfloat16 h1 = __float2bfloat16(v1);
                    __nv_bfloat162 hh; hh.x = h0; hh.y = h1;
                    __nv_bfloat162 ll;
                    ll.x = __float2bfloat16(v0 - __bfloat162float(h0));
                    ll.y = __float2bfloat16(v1 - __bfloat162float(h1));
                    long long o = hv ? o1 : o0;
                    *(__nv_bfloat162*)(Ch + o) = hh;
                    *(__nv_bfloat162*)(Cl + o) = ll;
                }
            }
        }
    }
}

// ---------------- elementwise split-convert (x) ----------------
__global__ __launch_bounds__(256) void convert_split(
    const float* __restrict__ x, __nv_bfloat16* __restrict__ h,
    __nv_bfloat16* __restrict__ l, int n4)
{
    int i = blockIdx.x * 256 + threadIdx.x;
    if (i >= n4) return;
    float4 v = ((const float4*)x)[i];
    __nv_bfloat16 h0 = __float2bfloat16(v.x), h1 = __float2bfloat16(v.y);
    __nv_bfloat16 h2 = __float2bfloat16(v.z), h3 = __float2bfloat16(v.w);
    __nv_bfloat162 ha; ha.x = h0; ha.y = h1;
    __nv_bfloat162 hb; hb.x = h2; hb.y = h3;
    __nv_bfloat162 la; la.x = __float2bfloat16(v.x - __bfloat162float(h0));
    la.y = __float2bfloat16(v.y - __bfloat162float(h1));
    __nv_bfloat162 lb; lb.x = __float2bfloat16(v.z - __bfloat162float(h2));
    lb.y = __float2bfloat16(v.w - __bfloat162float(h3));
    ((__nv_bfloat162*)h)[2*i]   = ha;
    ((__nv_bfloat162*)h)[2*i+1] = hb;
    ((__nv_bfloat162*)l)[2*i]   = la;
    ((__nv_bfloat162*)l)[2*i+1] = lb;
}

// ---------------- transpose + split-convert (W -> W^T) ----------------
__global__ __launch_bounds__(256) void wtrans_split(
    const float* __restrict__ W, __nv_bfloat16* __restrict__ th,
    __nv_bfloat16* __restrict__ tl)
{
    int idx = blockIdx.x * 256 + threadIdx.x;   // over 512*512
    int k = idx >> 9, n = idx & 511;
    float v = W[idx];                            // W[k][n], coalesced read
    __nv_bfloat16 h = __float2bfloat16(v);
    __nv_bfloat16 l = __float2bfloat16(v - __bfloat162float(h));
    th[n * 512 + k] = h;
    tl[n * 512 + k] = l;
}

// ---------------- softmax with fused bf16 split ----------------
__global__ __launch_bounds__(256) void softmax_split(
    const float* __restrict__ S, __nv_bfloat16* __restrict__ Ph,
    __nv_bfloat16* __restrict__ Pl)
{
    long long row = blockIdx.x;
    const float4* p = (const float4*)(S + row * SEQ);
    const int tid = threadIdx.x;
    const int wid = tid >> 5, lane = tid & 31;
    __shared__ float red[8];

    float4 v[4];
#pragma unroll
    for (int j = 0; j < 4; j++) v[j] = p[tid + j * 256];

    float m = -1e30f;
#pragma unroll
    for (int j = 0; j < 4; j++)
        m = fmaxf(m, fmaxf(fmaxf(v[j].x, v[j].y), fmaxf(v[j].z, v[j].w)));
#pragma unroll
    for (int o = 16; o > 0; o >>= 1) m = fmaxf(m, __shfl_xor_sync(0xFFFFFFFF, m, o));
    if (lane == 0) red[wid] = m;
    __syncthreads();
    m = red[0];
#pragma unroll
    for (int w = 1; w < 8; w++) m = fmaxf(m, red[w]);
    __syncthreads();

    float sum = 0.0f;
#pragma unroll
    for (int j = 0; j < 4; j++) {
        v[j].x = __expf(v[j].x - m); v[j].y = __expf(v[j].y - m);
        v[j].z = __expf(v[j].z - m); v[j].w = __expf(v[j].w - m);
        sum += v[j].x + v[j].y + v[j].z + v[j].w;
    }
#pragma unroll
    for (int o = 16; o > 0; o >>= 1) sum += __shfl_xor_sync(0xFFFFFFFF, sum, o);
    if (lane == 0) red[wid] = sum;
    __syncthreads();
    sum = 0.0f;
#pragma unroll
    for (int w = 0; w < 8; w++) sum += red[w];
    float inv = 1.0f / sum;

    __nv_bfloat162* dh = (__nv_bfloat162*)(Ph + row * SEQ);
    __nv_bfloat162* dl = (__nv_bfloat162*)(Pl + row * SEQ);
#pragma unroll
    for (int j = 0; j < 4; j++) {
        int e = (tid + j * 256) * 2;   // bf162 index
        float a = v[j].x * inv, b = v[j].y * inv, c = v[j].z * inv, d2 = v[j].w * inv;
        __nv_bfloat16 ha = __float2bfloat16(a), hb = __float2bfloat16(b);
        __nv_bfloat16 hc = __float2bfloat16(c), hd = __float2bfloat16(d2);
        __nv_bfloat162 p0; p0.x = ha; p0.y = hb;
        __nv_bfloat162 p1; p1.x = hc; p1.y = hd;
        __nv_bfloat162 q0; q0.x = __float2bfloat16(a - __bfloat162float(ha));
        q0.y = __float2bfloat16(b - __bfloat162float(hb));
        __nv_bfloat162 q1; q1.x = __float2bfloat16(c - __bfloat162float(hc));
        q1.y = __float2bfloat16(d2 - __bfloat162float(hd));
        dh[e] = p0; dh[e + 1] = p1;
        dl[e] = q0; dl[e + 1] = q1;
    }
}

// ---------------- host ----------------
extern "C" void kernel_launch(void* const* d_in, const int* in_sizes, int n_in,
                              void* d_out, int out_size)
{
    const float* x  = (const float*)d_in[0];
    const float* Wq = (const float*)d_in[1];
    const float* Wk = (const float*)d_in[2];
    const float* Wv = (const float*)d_in[3];
    float* out = (float*)d_out;

    __nv_bfloat16 *xh, *xl, *Wqth, *Wqtl, *Wkth, *Wktl, *Wvth, *Wvtl;
    __nv_bfloat16 *Qh, *Ql, *Kh, *Kl, *Vth, *Vtl, *Ph, *Pl;
    float* S;
    cudaGetSymbolAddress((void**)&xh, g_xh);   cudaGetSymbolAddress((void**)&xl, g_xl);
    cudaGetSymbolAddress((void**)&Wqth, g_Wqth); cudaGetSymbolAddress((void**)&Wqtl, g_Wqtl);
    cudaGetSymbolAddress((void**)&Wkth, g_Wkth); cudaGetSymbolAddress((void**)&Wktl, g_Wktl);
    cudaGetSymbolAddress((void**)&Wvth, g_Wvth); cudaGetSymbolAddress((void**)&Wvtl, g_Wvtl);
    cudaGetSymbolAddress((void**)&Qh, g_Qh);   cudaGetSymbolAddress((void**)&Ql, g_Ql);
    cudaGetSymbolAddress((void**)&Kh, g_Kh);   cudaGetSymbolAddress((void**)&Kl, g_Kl);
    cudaGetSymbolAddress((void**)&Vth, g_Vth); cudaGetSymbolAddress((void**)&Vtl, g_Vtl);
    cudaGetSymbolAddress((void**)&Ph, g_Ph);   cudaGetSymbolAddress((void**)&Pl, g_Pl);
    cudaGetSymbolAddress((void**)&S, g_S);

    cudaFuncSetAttribute(mma_gemm<0>, cudaFuncAttributeMaxDynamicSharedMemorySize, GSMEM);
    cudaFuncSetAttribute(mma_gemm<1>, cudaFuncAttributeMaxDynamicSharedMemorySize, GSMEM);

    // 1) split-convert x; transpose-split W
    convert_split<<<(MTOT*DM/4 + 255)/256, 256>>>(x, xh, xl, MTOT*DM/4);
    wtrans_split<<<DM*DM/256, 256>>>(Wq, Wqth, Wqtl);
    wtrans_split<<<DM*DM/256, 256>>>(Wk, Wkth, Wktl);
    wtrans_split<<<DM*DM/256, 256>>>(Wv, Wvth, Wvtl);

    // 2) Q = x@Wq, K = x@Wk  (split epilogue)
    {
        dim3 g(DM/128, MTOT/128, 1);
        mma_gemm<1><<<g, 256, GSMEM>>>(xh, xl, Wqth, Wqtl, nullptr, Qh, Ql,
                                       DM, DM, DM, DM, 0, 0, 0, 1.0f);
        mma_gemm<1><<<g, 256, GSMEM>>>(xh, xl, Wkth, Wktl, nullptr, Kh, Kl,
                                       DM, DM, DM, DM, 0, 0, 0, 1.0f);
    }
    // 3) V^T = Wv^T @ x^T : A=Wvt [512,512], B=x [8192,512] -> C [512, 8192]
    {
        dim3 g(MTOT/128, DM/128, 1);
        mma_gemm<1><<<g, 256, GSMEM>>>(Wvth, Wvtl, xh, xl, nullptr, Vth, Vtl,
                                       DM, DM, DM, MTOT, 0, 0, 0, 1.0f);
    }
    // 4) scores = (Q @ K^T) / sqrt(512)  (fp32 epilogue)
    {
        dim3 g(SEQ/128, SEQ/128, BATCH);
        mma_gemm<0><<<g, 256, GSMEM>>>(Qh, Ql, Kh, Kl, S, nullptr, nullptr,
                                       DM, DM, DM, SEQ,
                                       (long long)SEQ*DM, (long long)SEQ*DM,
                                       (long long)SEQ*SEQ, 0.044194173824159216f);
    }
    // 5) softmax + split
    softmax_split<<<BATCH*SEQ, 256>>>(S, Ph, Pl);

    // 6) out = P @ V = P @ (V^T)^T : A=P[4096,4096(k)], B=Vt rows are n, k along 8192 cols
    {
        dim3 g(DM/128, SEQ/128, BATCH);
        mma_gemm<0><<<g, 256, GSMEM>>>(Ph, Pl, Vth, Vtl, out, nullptr, nullptr,
                                       SEQ, SEQ, MTOT, DM,
                                       (long long)SEQ*SEQ, (long long)SEQ,
                                       (long long)SEQ*DM, 1.0f);
    }
}

// round 9
// speedup vs baseline: 2.9242x; 1.2857x over previous
#include <cuda_runtime.h>
#include <cuda_bf16.h>
#include <cuda_fp16.h>
#include <cstdint>
#include <math.h>

#define BATCH 2
#define SEQ   4096
#define DM    512
#define MTOT  (BATCH*SEQ)            // 8192

// ---------------- device scratch (no allocs allowed) ----------------
__device__ __nv_bfloat16 g_xh[MTOT*DM], g_xl[MTOT*DM];                 // x split
__device__ __nv_bfloat16 g_Wqth[DM*DM], g_Wqtl[DM*DM];                 // W^T split
__device__ __nv_bfloat16 g_Wkth[DM*DM], g_Wktl[DM*DM];
__device__ __nv_bfloat16 g_Wvth[DM*DM], g_Wvtl[DM*DM];
__device__ __half        g_Qf[MTOT*DM];                                // Q fp16 (for scores)
__device__ __half        g_Kf[MTOT*DM];                                // K fp16
__device__ __nv_bfloat16 g_Vth[DM*MTOT], g_Vtl[DM*MTOT];               // V^T [512, 8192]
__device__ float         g_S[(long long)BATCH*SEQ*SEQ];                // scores fp32
__device__ __nv_bfloat16 g_Ph[(long long)BATCH*SEQ*SEQ];               // softmax split
__device__ __nv_bfloat16 g_Pl[(long long)BATCH*SEQ*SEQ];

// ---------------- PTX helpers ----------------
__device__ __forceinline__ uint32_t smem_u32(const void* p) {
    uint32_t a;
    asm("{ .reg .u64 t; cvta.to.shared.u64 t, %1; cvt.u32.u64 %0, t; }" : "=r"(a) : "l"(p));
    return a;
}
__device__ __forceinline__ void cpasync16(uint32_t dst, const void* src) {
    asm volatile("cp.async.cg.shared.global [%0], [%1], 16;" :: "r"(dst), "l"(src));
}
__device__ __forceinline__ void cp_commit() {
    asm volatile("cp.async.commit_group;" ::: "memory");
}
template<int N>
__device__ __forceinline__ void cp_wait() {
    asm volatile("cp.async.wait_group %0;" :: "n"(N) : "memory");
}
__device__ __forceinline__ void ldmx4(uint32_t* r, uint32_t addr) {
    asm volatile("ldmatrix.sync.aligned.m8n8.x4.shared.b16 {%0,%1,%2,%3}, [%4];"
                 : "=r"(r[0]), "=r"(r[1]), "=r"(r[2]), "=r"(r[3]) : "r"(addr));
}
__device__ __forceinline__ void mma16816(float* c, const uint32_t* a, const uint32_t* b) {
    asm volatile(
        "mma.sync.aligned.m16n8k16.row.col.f32.bf16.bf16.f32 "
        "{%0,%1,%2,%3}, {%4,%5,%6,%7}, {%8,%9}, {%0,%1,%2,%3};"
        : "+f"(c[0]), "+f"(c[1]), "+f"(c[2]), "+f"(c[3])
        : "r"(a[0]), "r"(a[1]), "r"(a[2]), "r"(a[3]), "r"(b[0]), "r"(b[1]));
}
__device__ __forceinline__ void mma16816h(float* c, const uint32_t* a, const uint32_t* b) {
    asm volatile(
        "mma.sync.aligned.m16n8k16.row.col.f32.f16.f16.f32 "
        "{%0,%1,%2,%3}, {%4,%5,%6,%7}, {%8,%9}, {%0,%1,%2,%3};"
        : "+f"(c[0]), "+f"(c[1]), "+f"(c[2]), "+f"(c[3])
        : "r"(a[0]), "r"(a[1]), "r"(a[2]), "r"(a[3]), "r"(b[0]), "r"(b[1]));
}

// ---------------- shared tiling constants ----------------
#define ROWB    80                 // padded row stride in bytes (40 bf16)
#define MAT_B   (128*ROWB)         // 10240 B per matrix tile
#define STAGE_B (4*MAT_B)          // 40960 B per stage (3-term kernel)
#define NSTAGE  3
#define GSMEM   (NSTAGE*STAGE_B + 128)

// ---------------- 3-term split-bf16 GEMM ----------------
// C[M,N] = alpha * A @ B^T  with A[M,K] (h/l), B[N,K] (h/l) row-major bf16.
// EPI==0: fp32 C.  EPI==1: bf16 split (Ch, Cl).  EPI==2: fp16 (via Ch cast).
template<int EPI>
__global__ __launch_bounds__(256, 1) void mma_gemm(
    const __nv_bfloat16* __restrict__ Ah, const __nv_bfloat16* __restrict__ Al,
    const __nv_bfloat16* __restrict__ Bh, const __nv_bfloat16* __restrict__ Bl,
    float* __restrict__ C, __nv_bfloat16* __restrict__ Ch, __nv_bfloat16* __restrict__ Cl,
    int K, int lda, int ldb, int ldc,
    long long sA, long long sB, long long sC, float alpha)
{
    extern __shared__ char dsm[];
    const uint32_t smem0 = (smem_u32(dsm) + 127) & ~127u;

    const int tid = threadIdx.x;
    const int lane = tid & 31;
    const int wid = tid >> 5;
    const int warpM = wid & 1;
    const int warpN = wid >> 1;
    const int g = lane >> 2;
    const int tig = lane & 3;

    const long long bz = blockIdx.z;
    Ah += bz * sA; Al += bz * sA;
    Bh += bz * sB; Bl += bz * sB;
    const int rowBase = blockIdx.y * 128;
    const int colBase = blockIdx.x * 128;

    const int q = tid & 3;
    const int rbase = tid >> 2;

    const __nv_bfloat16* srcA_h = Ah + (long long)rowBase * lda + q * 8;
    const __nv_bfloat16* srcA_l = Al + (long long)rowBase * lda + q * 8;
    const __nv_bfloat16* srcB_h = Bh + (long long)colBase * ldb + q * 8;
    const __nv_bfloat16* srcB_l = Bl + (long long)colBase * ldb + q * 8;

    auto load_stage = [&](int buf, int k0) {
        const uint32_t stg = smem0 + buf * STAGE_B;
#pragma unroll
        for (int i = 0; i < 8; i++) {
            const int mat = i >> 1;
            const int r = rbase + (i & 1) * 64;
            const uint32_t dst = stg + mat * MAT_B + r * ROWB + q * 16;
            const __nv_bfloat16* src;
            if (mat == 0)      src = srcA_h + (long long)r * lda + k0;
            else if (mat == 1) src = srcA_l + (long long)r * lda + k0;
            else if (mat == 2) src = srcB_h + (long long)r * ldb + k0;
            else               src = srcB_l + (long long)r * ldb + k0;
            cpasync16(dst, src);
        }
        cp_commit();
    };

    const int tile = lane >> 3, trow = lane & 7;
    const uint32_t aoff = (uint32_t)((warpM * 64 + ((tile & 1) << 3) + trow) * ROWB
                                     + ((tile >> 1) << 4));
    const uint32_t boff = (uint32_t)((warpN * 32 + ((tile >> 1) << 3) + trow) * ROWB
                                     + ((tile & 1) << 4));

    float acc[4][4][4];
#pragma unroll
    for (int mt = 0; mt < 4; mt++)
#pragma unroll
        for (int nt = 0; nt < 4; nt++)
#pragma unroll
            for (int v = 0; v < 4; v++) acc[mt][nt][v] = 0.0f;

    const int NC = K >> 5;
    load_stage(0, 0);
    if (NC > 1) load_stage(1, 32);

    for (int it = 0; it < NC; it++) {
        if (it + 2 < NC) { load_stage((it + 2) % NSTAGE, (it + 2) << 5); cp_wait<2>(); }
        else if (it + 1 < NC) { cp_wait<1>(); }
        else { cp_wait<0>(); }
        __syncthreads();

        const uint32_t stg = smem0 + (it % NSTAGE) * STAGE_B;
        const uint32_t sAh = stg;
        const uint32_t sAl = stg + MAT_B;
        const uint32_t sBh = stg + 2 * MAT_B;
        const uint32_t sBl = stg + 3 * MAT_B;

#pragma unroll
        for (int ks = 0; ks < 2; ks++) {
            const uint32_t kb = ks * 32;

            uint32_t ah[4][4], al[4][4], bh[4][2], bl[4][2];
#pragma unroll
            for (int mt = 0; mt < 4; mt++) {
                ldmx4(ah[mt], sAh + aoff + mt * (16 * ROWB) + kb);
                ldmx4(al[mt], sAl + aoff + mt * (16 * ROWB) + kb);
            }
#pragma unroll
            for (int p = 0; p < 2; p++) {
                ldmx4(&bh[2 * p][0], sBh + boff + p * (16 * ROWB) + kb);
                ldmx4(&bl[2 * p][0], sBl + boff + p * (16 * ROWB) + kb);
            }
#pragma unroll
            for (int mt = 0; mt < 4; mt++)
#pragma unroll
                for (int nt = 0; nt < 4; nt++) {
                    mma16816(acc[mt][nt], ah[mt], bh[nt]);
                    mma16816(acc[mt][nt], ah[mt], bl[nt]);
                    mma16816(acc[mt][nt], al[mt], bh[nt]);
                }
        }
        __syncthreads();
    }

    // ---- epilogue ----
#pragma unroll
    for (int mt = 0; mt < 4; mt++) {
#pragma unroll
        for (int nt = 0; nt < 4; nt++) {
            const int row = rowBase + warpM * 64 + mt * 16 + g;
            const int col = colBase + warpN * 32 + nt * 8 + tig * 2;
            if (EPI == 0) {
                float2 v0 = make_float2(acc[mt][nt][0] * alpha, acc[mt][nt][1] * alpha);
                float2 v1 = make_float2(acc[mt][nt][2] * alpha, acc[mt][nt][3] * alpha);
                float* base = C + bz * sC;
                *(float2*)(base + (long long)row * ldc + col) = v0;
                *(float2*)(base + (long long)(row + 8) * ldc + col) = v1;
            } else if (EPI == 1) {
                long long o0 = (long long)row * ldc + col;
                long long o1 = (long long)(row + 8) * ldc + col;
#pragma unroll
                for (int hv = 0; hv < 2; hv++) {
                    float v0 = acc[mt][nt][hv * 2 + 0];
                    float v1 = acc[mt][nt][hv * 2 + 1];
                    __nv_bfloat16 h0 = __float2bfloat16(v0);
                    __nv_bfloat16 h1 = __float2bfloat16(v1);
                    __nv_bfloat162 hh; hh.x = h0; hh.y = h1;
                    __nv_bfloat162 ll;
                    ll.x = __float2bfloat16(v0 - __bfloat162float(h0));
                    ll.y = __float2bfloat16(v1 - __bfloat162float(h1));
                    long long o = hv ? o1 : o0;
                    *(__nv_bfloat162*)(Ch + o) = hh;
                    *(__nv_bfloat162*)(Cl + o) = ll;
                }
            } else {
                __half* Cf = (__half*)Ch;
                long long o0 = (long long)row * ldc + col;
                long long o1 = (long long)(row + 8) * ldc + col;
                *(__half2*)(Cf + o0) = __floats2half2_rn(acc[mt][nt][0], acc[mt][nt][1]);
                *(__half2*)(Cf + o1) = __floats2half2_rn(acc[mt][nt][2], acc[mt][nt][3]);
            }
        }
    }
}

// ---------------- single-term fp16 GEMM (scores) ----------------
// C[M,N] = alpha * A @ B^T, A[M,K], B[N,K] fp16 row-major, fp32 accum.
#define F16_STAGE_B (2*MAT_B)      // 20480 B per stage
#define F16_NSTAGE  3
#define GSMEM_F16   (F16_NSTAGE*F16_STAGE_B + 128)

__global__ __launch_bounds__(256, 2) void gemm_f16(
    const __half* __restrict__ A, const __half* __restrict__ B, float* __restrict__ C,
    int K, int lda, int ldb, int ldc,
    long long sA, long long sB, long long sC, float alpha)
{
    extern __shared__ char dsm[];
    const uint32_t smem0 = (smem_u32(dsm) + 127) & ~127u;

    const int tid = threadIdx.x;
    const int lane = tid & 31;
    const int wid = tid >> 5;
    const int warpM = wid & 1;
    const int warpN = wid >> 1;
    const int g = lane >> 2;
    const int tig = lane & 3;

    const long long bz = blockIdx.z;
    A += bz * sA;
    B += bz * sB;
    const int rowBase = blockIdx.y * 128;
    const int colBase = blockIdx.x * 128;

    const int q = tid & 3;
    const int rbase = tid >> 2;

    const __half* srcA = A + (long long)rowBase * lda + q * 8;
    const __half* srcB = B + (long long)colBase * ldb + q * 8;

    auto load_stage = [&](int buf, int k0) {
        const uint32_t stg = smem0 + buf * F16_STAGE_B;
#pragma unroll
        for (int i = 0; i < 4; i++) {
            const int mat = i >> 1;
            const int r = rbase + (i & 1) * 64;
            const uint32_t dst = stg + mat * MAT_B + r * ROWB + q * 16;
            const __half* src = (mat == 0) ? srcA + (long long)r * lda + k0
                                           : srcB + (long long)r * ldb + k0;
            cpasync16(dst, src);
        }
        cp_commit();
    };

    const int tile = lane >> 3, trow = lane & 7;
    const uint32_t aoff = (uint32_t)((warpM * 64 + ((tile & 1) << 3) + trow) * ROWB
                                     + ((tile >> 1) << 4));
    const uint32_t boff = (uint32_t)((warpN * 32 + ((tile >> 1) << 3) + trow) * ROWB
                                     + ((tile & 1) << 4));

    float acc[4][4][4];
#pragma unroll
    for (int mt = 0; mt < 4; mt++)
#pragma unroll
        for (int nt = 0; nt < 4; nt++)
#pragma unroll
            for (int v = 0; v < 4; v++) acc[mt][nt][v] = 0.0f;

    const int NC = K >> 5;
    load_stage(0, 0);
    if (NC > 1) load_stage(1, 32);

    for (int it = 0; it < NC; it++) {
        if (it + 2 < NC) { load_stage((it + 2) % F16_NSTAGE, (it + 2) << 5); cp_wait<2>(); }
        else if (it + 1 < NC) { cp_wait<1>(); }
        else { cp_wait<0>(); }
        __syncthreads();

        const uint32_t stg = smem0 + (it % F16_NSTAGE) * F16_STAGE_B;
        const uint32_t sA = stg;
        const uint32_t sB = stg + MAT_B;

#pragma unroll
        for (int ks = 0; ks < 2; ks++) {
            const uint32_t kb = ks * 32;
            uint32_t af[4][4], bf[4][2];
#pragma unroll
            for (int mt = 0; mt < 4; mt++)
                ldmx4(af[mt], sA + aoff + mt * (16 * ROWB) + kb);
#pragma unroll
            for (int p = 0; p < 2; p++)
                ldmx4(&bf[2 * p][0], sB + boff + p * (16 * ROWB) + kb);
#pragma unroll
            for (int mt = 0; mt < 4; mt++)
#pragma unroll
                for (int nt = 0; nt < 4; nt++)
                    mma16816h(acc[mt][nt], af[mt], bf[nt]);
        }
        __syncthreads();
    }

#pragma unroll
    for (int mt = 0; mt < 4; mt++) {
#pragma unroll
        for (int nt = 0; nt < 4; nt++) {
            const int row = rowBase + warpM * 64 + mt * 16 + g;
            const int col = colBase + warpN * 32 + nt * 8 + tig * 2;
            float2 v0 = make_float2(acc[mt][nt][0] * alpha, acc[mt][nt][1] * alpha);
            float2 v1 = make_float2(acc[mt][nt][2] * alpha, acc[mt][nt][3] * alpha);
            float* base = C + bz * sC;
            *(float2*)(base + (long long)row * ldc + col) = v0;
            *(float2*)(base + (long long)(row + 8) * ldc + col) = v1;
        }
    }
}

// ---------------- elementwise split-convert (x) ----------------
__global__ __launch_bounds__(256) void convert_split(
    const float* __restrict__ x, __nv_bfloat16* __restrict__ h,
    __nv_bfloat16* __restrict__ l, int n4)
{
    int i = blockIdx.x * 256 + threadIdx.x;
    if (i >= n4) return;
    float4 v = ((const float4*)x)[i];
    __nv_bfloat16 h0 = __float2bfloat16(v.x), h1 = __float2bfloat16(v.y);
    __nv_bfloat16 h2 = __float2bfloat16(v.z), h3 = __float2bfloat16(v.w);
    __nv_bfloat162 ha; ha.x = h0; ha.y = h1;
    __nv_bfloat162 hb; hb.x = h2; hb.y = h3;
    __nv_bfloat162 la; la.x = __float2bfloat16(v.x - __bfloat162float(h0));
    la.y = __float2bfloat16(v.y - __bfloat162float(h1));
    __nv_bfloat162 lb; lb.x = __float2bfloat16(v.z - __bfloat162float(h2));
    lb.y = __float2bfloat16(v.w - __bfloat162float(h3));
    ((__nv_bfloat162*)h)[2*i]   = ha;
    ((__nv_bfloat162*)h)[2*i+1] = hb;
    ((__nv_bfloat162*)l)[2*i]   = la;
    ((__nv_bfloat162*)l)[2*i+1] = lb;
}

// ---------------- transpose + split-convert (W -> W^T) ----------------
__global__ __launch_bounds__(256) void wtrans_split(
    const float* __restrict__ W, __nv_bfloat16* __restrict__ th,
    __nv_bfloat16* __restrict__ tl)
{
    int idx = blockIdx.x * 256 + threadIdx.x;
    int k = idx >> 9, n = idx & 511;
    float v = W[idx];
    __nv_bfloat16 h = __float2bfloat16(v);
    __nv_bfloat16 l = __float2bfloat16(v - __bfloat162float(h));
    th[n * 512 + k] = h;
    tl[n * 512 + k] = l;
}

// ---------------- softmax with fused bf16 split ----------------
__global__ __launch_bounds__(256) void softmax_split(
    const float* __restrict__ S, __nv_bfloat16* __restrict__ Ph,
    __nv_bfloat16* __restrict__ Pl)
{
    long long row = blockIdx.x;
    const float4* p = (const float4*)(S + row * SEQ);
    const int tid = threadIdx.x;
    const int wid = tid >> 5, lane = tid & 31;
    __shared__ float red[8];

    float4 v[4];
#pragma unroll
    for (int j = 0; j < 4; j++) v[j] = p[tid + j * 256];

    float m = -1e30f;
#pragma unroll
    for (int j = 0; j < 4; j++)
        m = fmaxf(m, fmaxf(fmaxf(v[j].x, v[j].y), fmaxf(v[j].z, v[j].w)));
#pragma unroll
    for (int o = 16; o > 0; o >>= 1) m = fmaxf(m, __shfl_xor_sync(0xFFFFFFFF, m, o));
    if (lane == 0) red[wid] = m;
    __syncthreads();
    m = red[0];
#pragma unroll
    for (int w = 1; w < 8; w++) m = fmaxf(m, red[w]);
    __syncthreads();

    float sum = 0.0f;
#pragma unroll
    for (int j = 0; j < 4; j++) {
        v[j].x = __expf(v[j].x - m); v[j].y = __expf(v[j].y - m);
        v[j].z = __expf(v[j].z - m); v[j].w = __expf(v[j].w - m);
        sum += v[j].x + v[j].y + v[j].z + v[j].w;
    }
#pragma unroll
    for (int o = 16; o > 0; o >>= 1) sum += __shfl_xor_sync(0xFFFFFFFF, sum, o);
    if (lane == 0) red[wid] = sum;
    __syncthreads();
    sum = 0.0f;
#pragma unroll
    for (int w = 0; w < 8; w++) sum += red[w];
    float inv = 1.0f / sum;

    __nv_bfloat162* dh = (__nv_bfloat162*)(Ph + row * SEQ);
    __nv_bfloat162* dl = (__nv_bfloat162*)(Pl + row * SEQ);
#pragma unroll
    for (int j = 0; j < 4; j++) {
        int e = (tid + j * 256) * 2;
        float a = v[j].x * inv, b = v[j].y * inv, c = v[j].z * inv, d2 = v[j].w * inv;
        __nv_bfloat16 ha = __float2bfloat16(a), hb = __float2bfloat16(b);
        __nv_bfloat16 hc = __float2bfloat16(c), hd = __float2bfloat16(d2);
        __nv_bfloat162 p0; p0.x = ha; p0.y = hb;
        __nv_bfloat162 p1; p1.x = hc; p1.y = hd;
        __nv_bfloat162 q0; q0.x = __float2bfloat16(a - __bfloat162float(ha));
        q0.y = __float2bfloat16(b - __bfloat162float(hb));
        __nv_bfloat162 q1; q1.x = __float2bfloat16(c - __bfloat162float(hc));
        q1.y = __float2bfloat16(d2 - __bfloat162float(hd));
        dh[e] = p0; dh[e + 1] = p1;
        dl[e] = q0; dl[e + 1] = q1;
    }
}

// ---------------- host ----------------
extern "C" void kernel_launch(void* const* d_in, const int* in_sizes, int n_in,
                              void* d_out, int out_size)
{
    const float* x  = (const float*)d_in[0];
    const float* Wq = (const float*)d_in[1];
    const float* Wk = (const float*)d_in[2];
    const float* Wv = (const float*)d_in[3];
    float* out = (float*)d_out;

    __nv_bfloat16 *xh, *xl, *Wqth, *Wqtl, *Wkth, *Wktl, *Wvth, *Wvtl;
    __nv_bfloat16 *Vth, *Vtl, *Ph, *Pl;
    __half *Qf, *Kf;
    float* S;
    cudaGetSymbolAddress((void**)&xh, g_xh);   cudaGetSymbolAddress((void**)&xl, g_xl);
    cudaGetSymbolAddress((void**)&Wqth, g_Wqth); cudaGetSymbolAddress((void**)&Wqtl, g_Wqtl);
    cudaGetSymbolAddress((void**)&Wkth, g_Wkth); cudaGetSymbolAddress((void**)&Wktl, g_Wktl);
    cudaGetSymbolAddress((void**)&Wvth, g_Wvth); cudaGetSymbolAddress((void**)&Wvtl, g_Wvtl);
    cudaGetSymbolAddress((void**)&Qf, g_Qf);   cudaGetSymbolAddress((void**)&Kf, g_Kf);
    cudaGetSymbolAddress((void**)&Vth, g_Vth); cudaGetSymbolAddress((void**)&Vtl, g_Vtl);
    cudaGetSymbolAddress((void**)&Ph, g_Ph);   cudaGetSymbolAddress((void**)&Pl, g_Pl);
    cudaGetSymbolAddress((void**)&S, g_S);

    cudaFuncSetAttribute(mma_gemm<0>, cudaFuncAttributeMaxDynamicSharedMemorySize, GSMEM);
    cudaFuncSetAttribute(mma_gemm<1>, cudaFuncAttributeMaxDynamicSharedMemorySize, GSMEM);
    cudaFuncSetAttribute(mma_gemm<2>, cudaFuncAttributeMaxDynamicSharedMemorySize, GSMEM);
    cudaFuncSetAttribute(gemm_f16, cudaFuncAttributeMaxDynamicSharedMemorySize, GSMEM_F16);

    // 1) split-convert x; transpose-split W
    convert_split<<<(MTOT*DM/4 + 255)/256, 256>>>(x, xh, xl, MTOT*DM/4);
    wtrans_split<<<DM*DM/256, 256>>>(Wq, Wqth, Wqtl);
    wtrans_split<<<DM*DM/256, 256>>>(Wk, Wkth, Wktl);
    wtrans_split<<<DM*DM/256, 256>>>(Wv, Wvth, Wvtl);

    // 2) Q = x@Wq, K = x@Wk  -> fp16 single output
    {
        dim3 g(DM/128, MTOT/128, 1);
        mma_gemm<2><<<g, 256, GSMEM>>>(xh, xl, Wqth, Wqtl, nullptr,
                                       (__nv_bfloat16*)Qf, nullptr,
                                       DM, DM, DM, DM, 0, 0, 0, 1.0f);
        mma_gemm<2><<<g, 256, GSMEM>>>(xh, xl, Wkth, Wktl, nullptr,
                                       (__nv_bfloat16*)Kf, nullptr,
                                       DM, DM, DM, DM, 0, 0, 0, 1.0f);
    }
    // 3) V^T = Wv^T @ x^T (bf16 split output)
    {
        dim3 g(MTOT/128, DM/128, 1);
        mma_gemm<1><<<g, 256, GSMEM>>>(Wvth, Wvtl, xh, xl, nullptr, Vth, Vtl,
                                       DM, DM, DM, MTOT, 0, 0, 0, 1.0f);
    }
    // 4) scores = (Qf @ Kf^T) / sqrt(512)  — single-term fp16
    {
        dim3 g(SEQ/128, SEQ/128, BATCH);
        gemm_f16<<<g, 256, GSMEM_F16>>>(Qf, Kf, S,
                                        DM, DM, DM, SEQ,
                                        (long long)SEQ*DM, (long long)SEQ*DM,
                                        (long long)SEQ*SEQ, 0.044194173824159216f);
    }
    // 5) softmax + split
    softmax_split<<<BATCH*SEQ, 256>>>(S, Ph, Pl);

    // 6) out = P @ V  (3-term bf16, fp32 out)
    {
        dim3 g(DM/128, SEQ/128, BATCH);
        mma_gemm<0><<<g, 256, GSMEM>>>(Ph, Pl, Vth, Vtl, out, nullptr, nullptr,
                                       SEQ, SEQ, MTOT, DM,
                                       (long long)SEQ*SEQ, (long long)SEQ,
                                       (long long)SEQ*DM, 1.0f);
    }
}

// round 12
// speedup vs baseline: 4.3593x; 1.4908x over previous
#include <cuda_runtime.h>
#include <cuda_bf16.h>
#include <cuda_fp16.h>
#include <cstdint>
#include <math.h>

#define BATCH 2
#define SEQ   4096
#define DM    512
#define MTOT  (BATCH*SEQ)            // 8192

// ---------------- device scratch (no allocs allowed) ----------------
__device__ __nv_bfloat16 g_xh[MTOT*DM], g_xl[MTOT*DM];                 // x split
__device__ __nv_bfloat16 g_Wqth[DM*DM], g_Wqtl[DM*DM];                 // W^T split
__device__ __nv_bfloat16 g_Wkth[DM*DM], g_Wktl[DM*DM];
__device__ __nv_bfloat16 g_Wvth[DM*DM], g_Wvtl[DM*DM];
__device__ __half        g_Qf[MTOT*DM];                                // Q fp16
__device__ __half        g_Kf[MTOT*DM];                                // K fp16
__device__ __half        g_Vtf[DM*MTOT];                               // V^T fp16 [512, 8192]
__device__ float         g_S[(long long)BATCH*SEQ*SEQ];                // scores fp32
__device__ __half        g_Pf[(long long)BATCH*SEQ*SEQ];               // softmax fp16

// ---------------- PTX helpers ----------------
__device__ __forceinline__ uint32_t smem_u32(const void* p) {
    uint32_t a;
    asm("{ .reg .u64 t; cvta.to.shared.u64 t, %1; cvt.u32.u64 %0, t; }" : "=r"(a) : "l"(p));
    return a;
}
__device__ __forceinline__ void cpasync16(uint32_t dst, const void* src) {
    asm volatile("cp.async.cg.shared.global [%0], [%1], 16;" :: "r"(dst), "l"(src));
}
__device__ __forceinline__ void cp_commit() {
    asm volatile("cp.async.commit_group;" ::: "memory");
}
template<int N>
__device__ __forceinline__ void cp_wait() {
    asm volatile("cp.async.wait_group %0;" :: "n"(N) : "memory");
}
__device__ __forceinline__ void ldmx4(uint32_t* r, uint32_t addr) {
    asm volatile("ldmatrix.sync.aligned.m8n8.x4.shared.b16 {%0,%1,%2,%3}, [%4];"
                 : "=r"(r[0]), "=r"(r[1]), "=r"(r[2]), "=r"(r[3]) : "r"(addr));
}
__device__ __forceinline__ void mma16816(float* c, const uint32_t* a, const uint32_t* b) {
    asm volatile(
        "mma.sync.aligned.m16n8k16.row.col.f32.bf16.bf16.f32 "
        "{%0,%1,%2,%3}, {%4,%5,%6,%7}, {%8,%9}, {%0,%1,%2,%3};"
        : "+f"(c[0]), "+f"(c[1]), "+f"(c[2]), "+f"(c[3])
        : "r"(a[0]), "r"(a[1]), "r"(a[2]), "r"(a[3]), "r"(b[0]), "r"(b[1]));
}
__device__ __forceinline__ void mma16816h(float* c, const uint32_t* a, const uint32_t* b) {
    asm volatile(
        "mma.sync.aligned.m16n8k16.row.col.f32.f16.f16.f32 "
        "{%0,%1,%2,%3}, {%4,%5,%6,%7}, {%8,%9}, {%0,%1,%2,%3};"
        : "+f"(c[0]), "+f"(c[1]), "+f"(c[2]), "+f"(c[3])
        : "r"(a[0]), "r"(a[1]), "r"(a[2]), "r"(a[3]), "r"(b[0]), "r"(b[1]));
}

// ---------------- shared tiling constants ----------------
#define ROWB    80                 // padded row stride in bytes (40 bf16)
#define MAT_B   (128*ROWB)         // 10240 B per matrix tile
#define STAGE_B (4*MAT_B)          // 40960 B per stage (3-term kernel)
#define NSTAGE  3
#define GSMEM   (NSTAGE*STAGE_B + 128)

// ---------------- 3-term split-bf16 GEMM ----------------
// C[M,N] = alpha * A @ B^T  with A[M,K] (h/l), B[N,K] (h/l) row-major bf16.
// EPI==0: fp32 C.  EPI==2: fp16 (via Ch cast).
template<int EPI>
__global__ __launch_bounds__(256, 1) void mma_gemm(
    const __nv_bfloat16* __restrict__ Ah, const __nv_bfloat16* __restrict__ Al,
    const __nv_bfloat16* __restrict__ Bh, const __nv_bfloat16* __restrict__ Bl,
    float* __restrict__ C, __nv_bfloat16* __restrict__ Ch,
    int K, int lda, int ldb, int ldc,
    long long sA, long long sB, long long sC, float alpha)
{
    extern __shared__ char dsm[];
    const uint32_t smem0 = (smem_u32(dsm) + 127) & ~127u;

    const int tid = threadIdx.x;
    const int lane = tid & 31;
    const int wid = tid >> 5;
    const int warpM = wid & 1;
    const int warpN = wid >> 1;
    const int g = lane >> 2;
    const int tig = lane & 3;

    const long long bz = blockIdx.z;
    Ah += bz * sA; Al += bz * sA;
    Bh += bz * sB; Bl += bz * sB;
    const int rowBase = blockIdx.y * 128;
    const int colBase = blockIdx.x * 128;

    const int q = tid & 3;
    const int rbase = tid >> 2;

    const __nv_bfloat16* srcA_h = Ah + (long long)rowBase * lda + q * 8;
    const __nv_bfloat16* srcA_l = Al + (long long)rowBase * lda + q * 8;
    const __nv_bfloat16* srcB_h = Bh + (long long)colBase * ldb + q * 8;
    const __nv_bfloat16* srcB_l = Bl + (long long)colBase * ldb + q * 8;

    auto load_stage = [&](int buf, int k0) {
        const uint32_t stg = smem0 + buf * STAGE_B;
#pragma unroll
        for (int i = 0; i < 8; i++) {
            const int mat = i >> 1;
            const int r = rbase + (i & 1) * 64;
            const uint32_t dst = stg + mat * MAT_B + r * ROWB + q * 16;
            const __nv_bfloat16* src;
            if (mat == 0)      src = srcA_h + (long long)r * lda + k0;
            else if (mat == 1) src = srcA_l + (long long)r * lda + k0;
            else if (mat == 2) src = srcB_h + (long long)r * ldb + k0;
            else               src = srcB_l + (long long)r * ldb + k0;
            cpasync16(dst, src);
        }
        cp_commit();
    };

    const int tile = lane >> 3, trow = lane & 7;
    const uint32_t aoff = (uint32_t)((warpM * 64 + ((tile & 1) << 3) + trow) * ROWB
                                     + ((tile >> 1) << 4));
    const uint32_t boff = (uint32_t)((warpN * 32 + ((tile >> 1) << 3) + trow) * ROWB
                                     + ((tile & 1) << 4));

    float acc[4][4][4];
#pragma unroll
    for (int mt = 0; mt < 4; mt++)
#pragma unroll
        for (int nt = 0; nt < 4; nt++)
#pragma unroll
            for (int v = 0; v < 4; v++) acc[mt][nt][v] = 0.0f;

    const int NC = K >> 5;
    load_stage(0, 0);
    if (NC > 1) load_stage(1, 32);

    for (int it = 0; it < NC; it++) {
        if (it + 2 < NC) { load_stage((it + 2) % NSTAGE, (it + 2) << 5); cp_wait<2>(); }
        else if (it + 1 < NC) { cp_wait<1>(); }
        else { cp_wait<0>(); }
        __syncthreads();

        const uint32_t stg = smem0 + (it % NSTAGE) * STAGE_B;
        const uint32_t sAh = stg;
        const uint32_t sAl = stg + MAT_B;
        const uint32_t sBh = stg + 2 * MAT_B;
        const uint32_t sBl = stg + 3 * MAT_B;

#pragma unroll
        for (int ks = 0; ks < 2; ks++) {
            const uint32_t kb = ks * 32;

            uint32_t ah[4][4], al[4][4], bh[4][2], bl[4][2];
#pragma unroll
            for (int mt = 0; mt < 4; mt++) {
                ldmx4(ah[mt], sAh + aoff + mt * (16 * ROWB) + kb);
                ldmx4(al[mt], sAl + aoff + mt * (16 * ROWB) + kb);
            }
#pragma unroll
            for (int p = 0; p < 2; p++) {
                ldmx4(&bh[2 * p][0], sBh + boff + p * (16 * ROWB) + kb);
                ldmx4(&bl[2 * p][0], sBl + boff + p * (16 * ROWB) + kb);
            }
#pragma unroll
            for (int mt = 0; mt < 4; mt++)
#pragma unroll
                for (int nt = 0; nt < 4; nt++) {
                    mma16816(acc[mt][nt], ah[mt], bh[nt]);
                    mma16816(acc[mt][nt], ah[mt], bl[nt]);
                    mma16816(acc[mt][nt], al[mt], bh[nt]);
                }
        }
        __syncthreads();
    }

    // ---- epilogue ----
#pragma unroll
    for (int mt = 0; mt < 4; mt++) {
#pragma unroll
        for (int nt = 0; nt < 4; nt++) {
            const int row = rowBase + warpM * 64 + mt * 16 + g;
            const int col = colBase + warpN * 32 + nt * 8 + tig * 2;
            if (EPI == 0) {
                float2 v0 = make_float2(acc[mt][nt][0] * alpha, acc[mt][nt][1] * alpha);
                float2 v1 = make_float2(acc[mt][nt][2] * alpha, acc[mt][nt][3] * alpha);
                float* base = C + bz * sC;
                *(float2*)(base + (long long)row * ldc + col) = v0;
                *(float2*)(base + (long long)(row + 8) * ldc + col) = v1;
            } else {
                __half* Cf = (__half*)Ch;
                long long o0 = (long long)row * ldc + col;
                long long o1 = (long long)(row + 8) * ldc + col;
                *(__half2*)(Cf + o0) = __floats2half2_rn(acc[mt][nt][0], acc[mt][nt][1]);
                *(__half2*)(Cf + o1) = __floats2half2_rn(acc[mt][nt][2], acc[mt][nt][3]);
            }
        }
    }
}

// ---------------- single-term fp16 GEMM ----------------
// C[M,N] = alpha * A @ B^T, A[M,K], B[N,K] fp16 row-major, fp32 accum, fp32 out.
#define F16_STAGE_B (2*MAT_B)      // 20480 B per stage
#define F16_NSTAGE  3
#define GSMEM_F16   (F16_NSTAGE*F16_STAGE_B + 128)

__global__ __launch_bounds__(256, 2) void gemm_f16(
    const __half* __restrict__ A, const __half* __restrict__ B, float* __restrict__ C,
    int K, int lda, int ldb, int ldc,
    long long sA, long long sB, long long sC, float alpha)
{
    extern __shared__ char dsm[];
    const uint32_t smem0 = (smem_u32(dsm) + 127) & ~127u;

    const int tid = threadIdx.x;
    const int lane = tid & 31;
    const int wid = tid >> 5;
    const int warpM = wid & 1;
    const int warpN = wid >> 1;
    const int g = lane >> 2;
    const int tig = lane & 3;

    const long long bz = blockIdx.z;
    A += bz * sA;
    B += bz * sB;
    const int rowBase = blockIdx.y * 128;
    const int colBase = blockIdx.x * 128;

    const int q = tid & 3;
    const int rbase = tid >> 2;

    const __half* srcA = A + (long long)rowBase * lda + q * 8;
    const __half* srcB = B + (long long)colBase * ldb + q * 8;

    auto load_stage = [&](int buf, int k0) {
        const uint32_t stg = smem0 + buf * F16_STAGE_B;
#pragma unroll
        for (int i = 0; i < 4; i++) {
            const int mat = i >> 1;
            const int r = rbase + (i & 1) * 64;
            const uint32_t dst = stg + mat * MAT_B + r * ROWB + q * 16;
            const __half* src = (mat == 0) ? srcA + (long long)r * lda + k0
                                           : srcB + (long long)r * ldb + k0;
            cpasync16(dst, src);
        }
        cp_commit();
    };

    const int tile = lane >> 3, trow = lane & 7;
    const uint32_t aoff = (uint32_t)((warpM * 64 + ((tile & 1) << 3) + trow) * ROWB
                                     + ((tile >> 1) << 4));
    const uint32_t boff = (uint32_t)((warpN * 32 + ((tile >> 1) << 3) + trow) * ROWB
                                     + ((tile & 1) << 4));

    float acc[4][4][4];
#pragma unroll
    for (int mt = 0; mt < 4; mt++)
#pragma unroll
        for (int nt = 0; nt < 4; nt++)
#pragma unroll
            for (int v = 0; v < 4; v++) acc[mt][nt][v] = 0.0f;

    const int NC = K >> 5;
    load_stage(0, 0);
    if (NC > 1) load_stage(1, 32);

    for (int it = 0; it < NC; it++) {
        if (it + 2 < NC) { load_stage((it + 2) % F16_NSTAGE, (it + 2) << 5); cp_wait<2>(); }
        else if (it + 1 < NC) { cp_wait<1>(); }
        else { cp_wait<0>(); }
        __syncthreads();

        const uint32_t stg = smem0 + (it % F16_NSTAGE) * F16_STAGE_B;
        const uint32_t sA = stg;
        const uint32_t sB = stg + MAT_B;

#pragma unroll
        for (int ks = 0; ks < 2; ks++) {
            const uint32_t kb = ks * 32;
            uint32_t af[4][4], bf[4][2];
#pragma unroll
            for (int mt = 0; mt < 4; mt++)
                ldmx4(af[mt], sA + aoff + mt * (16 * ROWB) + kb);
#pragma unroll
            for (int p = 0; p < 2; p++)
                ldmx4(&bf[2 * p][0], sB + boff + p * (16 * ROWB) + kb);
#pragma unroll
            for (int mt = 0; mt < 4; mt++)
#pragma unroll
                for (int nt = 0; nt < 4; nt++)
                    mma16816h(acc[mt][nt], af[mt], bf[nt]);
        }
        __syncthreads();
    }

#pragma unroll
    for (int mt = 0; mt < 4; mt++) {
#pragma unroll
        for (int nt = 0; nt < 4; nt++) {
            const int row = rowBase + warpM * 64 + mt * 16 + g;
            const int col = colBase + warpN * 32 + nt * 8 + tig * 2;
            float2 v0 = make_float2(acc[mt][nt][0] * alpha, acc[mt][nt][1] * alpha);
            float2 v1 = make_float2(acc[mt][nt][2] * alpha, acc[mt][nt][3] * alpha);
            float* base = C + bz * sC;
            *(float2*)(base + (long long)row * ldc + col) = v0;
            *(float2*)(base + (long long)(row + 8) * ldc + col) = v1;
        }
    }
}

// ---------------- elementwise split-convert (x) ----------------
__global__ __launch_bounds__(256) void convert_split(
    const float* __restrict__ x, __nv_bfloat16* __restrict__ h,
    __nv_bfloat16* __restrict__ l, int n4)
{
    int i = blockIdx.x * 256 + threadIdx.x;
    if (i >= n4) return;
    float4 v = ((const float4*)x)[i];
    __nv_bfloat16 h0 = __float2bfloat16(v.x), h1 = __float2bfloat16(v.y);
    __nv_bfloat16 h2 = __float2bfloat16(v.z), h3 = __float2bfloat16(v.w);
    __nv_bfloat162 ha; ha.x = h0; ha.y = h1;
    __nv_bfloat162 hb; hb.x = h2; hb.y = h3;
    __nv_bfloat162 la; la.x = __float2bfloat16(v.x - __bfloat162float(h0));
    la.y = __float2bfloat16(v.y - __bfloat162float(h1));
    __nv_bfloat162 lb; lb.x = __float2bfloat16(v.z - __bfloat162float(h2));
    lb.y = __float2bfloat16(v.w - __bfloat162float(h3));
    ((__nv_bfloat162*)h)[2*i]   = ha;
    ((__nv_bfloat162*)h)[2*i+1] = hb;
    ((__nv_bfloat162*)l)[2*i]   = la;
    ((__nv_bfloat162*)l)[2*i+1] = lb;
}

// ---------------- transpose + split-convert (W -> W^T) ----------------
__global__ __launch_bounds__(256) void wtrans_split(
    const float* __restrict__ W, __nv_bfloat16* __restrict__ th,
    __nv_bfloat16* __restrict__ tl)
{
    int idx = blockIdx.x * 256 + threadIdx.x;
    int k = idx >> 9, n = idx & 511;
    float v = W[idx];
    __nv_bfloat16 h = __float2bfloat16(v);
    __nv_bfloat16 l = __float2bfloat16(v - __bfloat162float(h));
    th[n * 512 + k] = h;
    tl[n * 512 + k] = l;
}

// ---------------- softmax -> fp16 P ----------------
__global__ __launch_bounds__(256) void softmax_f16(
    const float* __restrict__ S, __half* __restrict__ Pf)
{
    long long row = blockIdx.x;
    const float4* p = (const float4*)(S + row * SEQ);
    const int tid = threadIdx.x;
    const int wid = tid >> 5, lane = tid & 31;
    __shared__ float red[8];

    float4 v[4];
#pragma unroll
    for (int j = 0; j < 4; j++) v[j] = p[tid + j * 256];

    float m = -1e30f;
#pragma unroll
    for (int j = 0; j < 4; j++)
        m = fmaxf(m, fmaxf(fmaxf(v[j].x, v[j].y), fmaxf(v[j].z, v[j].w)));
#pragma unroll
    for (int o = 16; o > 0; o >>= 1) m = fmaxf(m, __shfl_xor_sync(0xFFFFFFFF, m, o));
    if (lane == 0) red[wid] = m;
    __syncthreads();
    m = red[0];
#pragma unroll
    for (int w = 1; w < 8; w++) m = fmaxf(m, red[w]);
    __syncthreads();

    float sum = 0.0f;
#pragma unroll
    for (int j = 0; j < 4; j++) {
        v[j].x = __expf(v[j].x - m); v[j].y = __expf(v[j].y - m);
        v[j].z = __expf(v[j].z - m); v[j].w = __expf(v[j].w - m);
        sum += v[j].x + v[j].y + v[j].z + v[j].w;
    }
#pragma unroll
    for (int o = 16; o > 0; o >>= 1) sum += __shfl_xor_sync(0xFFFFFFFF, sum, o);
    if (lane == 0) red[wid] = sum;
    __syncthreads();
    sum = 0.0f;
#pragma unroll
    for (int w = 0; w < 8; w++) sum += red[w];
    float inv = 1.0f / sum;

    __half2* dst = (__half2*)(Pf + row * SEQ);
#pragma unroll
    for (int j = 0; j < 4; j++) {
        int e = (tid + j * 256) * 2;
        dst[e]     = __floats2half2_rn(v[j].x * inv, v[j].y * inv);
        dst[e + 1] = __floats2half2_rn(v[j].z * inv, v[j].w * inv);
    }
}

// ---------------- host ----------------
extern "C" void kernel_launch(void* const* d_in, const int* in_sizes, int n_in,
                              void* d_out, int out_size)
{
    const float* x  = (const float*)d_in[0];
    const float* Wq = (const float*)d_in[1];
    const float* Wk = (const float*)d_in[2];
    const float* Wv = (const float*)d_in[3];
    float* out = (float*)d_out;

    __nv_bfloat16 *xh, *xl, *Wqth, *Wqtl, *Wkth, *Wktl, *Wvth, *Wvtl;
    __half *Qf, *Kf, *Vtf, *Pf;
    float* S;
    cudaGetSymbolAddress((void**)&xh, g_xh);   cudaGetSymbolAddress((void**)&xl, g_xl);
    cudaGetSymbolAddress((void**)&Wqth, g_Wqth); cudaGetSymbolAddress((void**)&Wqtl, g_Wqtl);
    cudaGetSymbolAddress((void**)&Wkth, g_Wkth); cudaGetSymbolAddress((void**)&Wktl, g_Wktl);
    cudaGetSymbolAddress((void**)&Wvth, g_Wvth); cudaGetSymbolAddress((void**)&Wvtl, g_Wvtl);
    cudaGetSymbolAddress((void**)&Qf, g_Qf);   cudaGetSymbolAddress((void**)&Kf, g_Kf);
    cudaGetSymbolAddress((void**)&Vtf, g_Vtf);
    cudaGetSymbolAddress((void**)&Pf, g_Pf);
    cudaGetSymbolAddress((void**)&S, g_S);

    cudaFuncSetAttribute(mma_gemm<2>, cudaFuncAttributeMaxDynamicSharedMemorySize, GSMEM);
    cudaFuncSetAttribute(gemm_f16, cudaFuncAttributeMaxDynamicSharedMemorySize, GSMEM_F16);

    // 1) split-convert x; transpose-split W
    convert_split<<<(MTOT*DM/4 + 255)/256, 256>>>(x, xh, xl, MTOT*DM/4);
    wtrans_split<<<DM*DM/256, 256>>>(Wq, Wqth, Wqtl);
    wtrans_split<<<DM*DM/256, 256>>>(Wk, Wkth, Wktl);
    wtrans_split<<<DM*DM/256, 256>>>(Wv, Wvth, Wvtl);

    // 2) Q = x@Wq, K = x@Wk  -> fp16 output (3-term bf16 compute)
    {
        dim3 g(DM/128, MTOT/128, 1);
        mma_gemm<2><<<g, 256, GSMEM>>>(xh, xl, Wqth, Wqtl, nullptr,
                                       (__nv_bfloat16*)Qf,
                                       DM, DM, DM, DM, 0, 0, 0, 1.0f);
        mma_gemm<2><<<g, 256, GSMEM>>>(xh, xl, Wkth, Wktl, nullptr,
                                       (__nv_bfloat16*)Kf,
                                       DM, DM, DM, DM, 0, 0, 0, 1.0f);
    }
    // 3) V^T = Wv^T @ x^T -> fp16 output [512, 8192]
    {
        dim3 g(MTOT/128, DM/128, 1);
        mma_gemm<2><<<g, 256, GSMEM>>>(Wvth, Wvtl, xh, xl, nullptr,
                                       (__nv_bfloat16*)Vtf,
                                       DM, DM, DM, MTOT, 0, 0, 0, 1.0f);
    }
    // 4) scores = (Qf @ Kf^T) / sqrt(512)  — single-term fp16
    {
        dim3 g(SEQ/128, SEQ/128, BATCH);
        gemm_f16<<<g, 256, GSMEM_F16>>>(Qf, Kf, S,
                                        DM, DM, DM, SEQ,
                                        (long long)SEQ*DM, (long long)SEQ*DM,
                                        (long long)SEQ*SEQ, 0.044194173824159216f);
    }
    // 5) softmax -> fp16 P
    softmax_f16<<<BATCH*SEQ, 256>>>(S, Pf);

    // 6) out = Pf @ Vtf^T  — single-term fp16
    {
        dim3 g(DM/128, SEQ/128, BATCH);
        gemm_f16<<<g, 256, GSMEM_F16>>>(Pf, Vtf, out,
                                        SEQ, SEQ, MTOT, DM,
                                        (long long)SEQ*SEQ, (long long)SEQ,
                                        (long long)SEQ*DM, 1.0f);
    }
}

// round 14
// speedup vs baseline: 5.3651x; 1.2307x over previous
#include <cuda_runtime.h>
#include <cuda_fp16.h>
#include <cstdint>
#include <math.h>

#define BATCH 2
#define SEQ   4096
#define DM    512
#define MTOT  (BATCH*SEQ)            // 8192

// ---------------- device scratch (no allocs allowed) ----------------
__device__ __half g_xf[MTOT*DM];                                 // x fp16
__device__ __half g_Wqt[DM*DM], g_Wkt[DM*DM], g_Wvt[DM*DM];      // W^T fp16
__device__ __half g_Qf[MTOT*DM];                                 // Q fp16
__device__ __half g_Kf[MTOT*DM];                                 // K fp16
__device__ __half g_Vtf[DM*MTOT];                                // V^T fp16 [512, 8192]
__device__ float  g_S[(long long)BATCH*SEQ*SEQ];                 // scores fp32
__device__ __half g_Pf[(long long)BATCH*SEQ*SEQ];                // softmax fp16

// ---------------- PTX helpers ----------------
__device__ __forceinline__ uint32_t smem_u32(const void* p) {
    uint32_t a;
    asm("{ .reg .u64 t; cvta.to.shared.u64 t, %1; cvt.u32.u64 %0, t; }" : "=r"(a) : "l"(p));
    return a;
}
__device__ __forceinline__ void cpasync16(uint32_t dst, const void* src) {
    asm volatile("cp.async.cg.shared.global [%0], [%1], 16;" :: "r"(dst), "l"(src));
}
__device__ __forceinline__ void cp_commit() {
    asm volatile("cp.async.commit_group;" ::: "memory");
}
template<int N>
__device__ __forceinline__ void cp_wait() {
    asm volatile("cp.async.wait_group %0;" :: "n"(N) : "memory");
}
__device__ __forceinline__ void ldmx4(uint32_t* r, uint32_t addr) {
    asm volatile("ldmatrix.sync.aligned.m8n8.x4.shared.b16 {%0,%1,%2,%3}, [%4];"
                 : "=r"(r[0]), "=r"(r[1]), "=r"(r[2]), "=r"(r[3]) : "r"(addr));
}
__device__ __forceinline__ void mma16816h(float* c, const uint32_t* a, const uint32_t* b) {
    asm volatile(
        "mma.sync.aligned.m16n8k16.row.col.f32.f16.f16.f32 "
        "{%0,%1,%2,%3}, {%4,%5,%6,%7}, {%8,%9}, {%0,%1,%2,%3};"
        : "+f"(c[0]), "+f"(c[1]), "+f"(c[2]), "+f"(c[3])
        : "r"(a[0]), "r"(a[1]), "r"(a[2]), "r"(a[3]), "r"(b[0]), "r"(b[1]));
}

// ---------------- tiling constants ----------------
#define ROWB    80                 // padded row stride in bytes (40 halves)
#define MAT_B   (128*ROWB)         // 10240 B per matrix tile
#define F16_STAGE_B (2*MAT_B)      // 20480 B per stage
#define F16_NSTAGE  3
#define GSMEM_F16   (F16_NSTAGE*F16_STAGE_B + 128)

// ---------------- single-term fp16 GEMM ----------------
// C[M,N] = alpha * A @ B^T, A[M,K], B[N,K] fp16 row-major, fp32 accum.
// EPI==0: fp32 out (C).  EPI==1: fp16 out (Cf).
template<int EPI>
__global__ __launch_bounds__(256, 2) void gemm_f16(
    const __half* __restrict__ A, const __half* __restrict__ B,
    float* __restrict__ C, __half* __restrict__ Cf,
    int K, int lda, int ldb, int ldc,
    long long sA, long long sB, long long sC, float alpha)
{
    extern __shared__ char dsm[];
    const uint32_t smem0 = (smem_u32(dsm) + 127) & ~127u;

    const int tid = threadIdx.x;
    const int lane = tid & 31;
    const int wid = tid >> 5;
    const int warpM = wid & 1;
    const int warpN = wid >> 1;
    const int g = lane >> 2;
    const int tig = lane & 3;

    const long long bz = blockIdx.z;
    A += bz * sA;
    B += bz * sB;
    const int rowBase = blockIdx.y * 128;
    const int colBase = blockIdx.x * 128;

    const int q = tid & 3;
    const int rbase = tid >> 2;

    const __half* srcA = A + (long long)rowBase * lda + q * 8;
    const __half* srcB = B + (long long)colBase * ldb + q * 8;

    auto load_stage = [&](int buf, int k0) {
        const uint32_t stg = smem0 + buf * F16_STAGE_B;
#pragma unroll
        for (int i = 0; i < 4; i++) {
            const int mat = i >> 1;
            const int r = rbase + (i & 1) * 64;
            const uint32_t dst = stg + mat * MAT_B + r * ROWB + q * 16;
            const __half* src = (mat == 0) ? srcA + (long long)r * lda + k0
                                           : srcB + (long long)r * ldb + k0;
            cpasync16(dst, src);
        }
        cp_commit();
    };

    const int tile = lane >> 3, trow = lane & 7;
    const uint32_t aoff = (uint32_t)((warpM * 64 + ((tile & 1) << 3) + trow) * ROWB
                                     + ((tile >> 1) << 4));
    const uint32_t boff = (uint32_t)((warpN * 32 + ((tile >> 1) << 3) + trow) * ROWB
                                     + ((tile & 1) << 4));

    float acc[4][4][4];
#pragma unroll
    for (int mt = 0; mt < 4; mt++)
#pragma unroll
        for (int nt = 0; nt < 4; nt++)
#pragma unroll
            for (int v = 0; v < 4; v++) acc[mt][nt][v] = 0.0f;

    const int NC = K >> 5;
    load_stage(0, 0);
    if (NC > 1) load_stage(1, 32);

    for (int it = 0; it < NC; it++) {
        if (it + 2 < NC) { load_stage((it + 2) % F16_NSTAGE, (it + 2) << 5); cp_wait<2>(); }
        else if (it + 1 < NC) { cp_wait<1>(); }
        else { cp_wait<0>(); }
        __syncthreads();

        const uint32_t stg = smem0 + (it % F16_NSTAGE) * F16_STAGE_B;
        const uint32_t sA = stg;
        const uint32_t sB = stg + MAT_B;

#pragma unroll
        for (int ks = 0; ks < 2; ks++) {
            const uint32_t kb = ks * 32;
            uint32_t af[4][4], bf[4][2];
#pragma unroll
            for (int mt = 0; mt < 4; mt++)
                ldmx4(af[mt], sA + aoff + mt * (16 * ROWB) + kb);
#pragma unroll
            for (int p = 0; p < 2; p++)
                ldmx4(&bf[2 * p][0], sB + boff + p * (16 * ROWB) + kb);
#pragma unroll
            for (int mt = 0; mt < 4; mt++)
#pragma unroll
                for (int nt = 0; nt < 4; nt++)
                    mma16816h(acc[mt][nt], af[mt], bf[nt]);
        }
        __syncthreads();
    }

#pragma unroll
    for (int mt = 0; mt < 4; mt++) {
#pragma unroll
        for (int nt = 0; nt < 4; nt++) {
            const int row = rowBase + warpM * 64 + mt * 16 + g;
            const int col = colBase + warpN * 32 + nt * 8 + tig * 2;
            if (EPI == 0) {
                float2 v0 = make_float2(acc[mt][nt][0] * alpha, acc[mt][nt][1] * alpha);
                float2 v1 = make_float2(acc[mt][nt][2] * alpha, acc[mt][nt][3] * alpha);
                float* base = C + bz * sC;
                *(float2*)(base + (long long)row * ldc + col) = v0;
                *(float2*)(base + (long long)(row + 8) * ldc + col) = v1;
            } else {
                long long o0 = (long long)row * ldc + col;
                long long o1 = (long long)(row + 8) * ldc + col;
                *(__half2*)(Cf + o0) = __floats2half2_rn(acc[mt][nt][0], acc[mt][nt][1]);
                *(__half2*)(Cf + o1) = __floats2half2_rn(acc[mt][nt][2], acc[mt][nt][3]);
            }
        }
    }
}

// ---------------- fp32 -> fp16 convert (x) ----------------
__global__ __launch_bounds__(256) void convert_f16(
    const float* __restrict__ x, __half* __restrict__ xf, int n4)
{
    int i = blockIdx.x * 256 + threadIdx.x;
    if (i >= n4) return;
    float4 v = ((const float4*)x)[i];
    ((__half2*)xf)[2*i]   = __floats2half2_rn(v.x, v.y);
    ((__half2*)xf)[2*i+1] = __floats2half2_rn(v.z, v.w);
}

// ---------------- transpose + fp16 convert (W -> W^T) ----------------
__global__ __launch_bounds__(256) void wtrans_f16(
    const float* __restrict__ W, __half* __restrict__ Wt)
{
    int idx = blockIdx.x * 256 + threadIdx.x;   // over 512*512
    int k = idx >> 9, n = idx & 511;
    Wt[n * 512 + k] = __float2half_rn(W[idx]);  // coalesced read, scattered write
}

// ---------------- softmax -> fp16 P ----------------
__global__ __launch_bounds__(256) void softmax_f16(
    const float* __restrict__ S, __half* __restrict__ Pf)
{
    long long row = blockIdx.x;
    const float4* p = (const float4*)(S + row * SEQ);
    const int tid = threadIdx.x;
    const int wid = tid >> 5, lane = tid & 31;
    __shared__ float red[8];

    float4 v[4];
#pragma unroll
    for (int j = 0; j < 4; j++) v[j] = p[tid + j * 256];

    float m = -1e30f;
#pragma unroll
    for (int j = 0; j < 4; j++)
        m = fmaxf(m, fmaxf(fmaxf(v[j].x, v[j].y), fmaxf(v[j].z, v[j].w)));
#pragma unroll
    for (int o = 16; o > 0; o >>= 1) m = fmaxf(m, __shfl_xor_sync(0xFFFFFFFF, m, o));
    if (lane == 0) red[wid] = m;
    __syncthreads();
    m = red[0];
#pragma unroll
    for (int w = 1; w < 8; w++) m = fmaxf(m, red[w]);
    __syncthreads();

    float sum = 0.0f;
#pragma unroll
    for (int j = 0; j < 4; j++) {
        v[j].x = __expf(v[j].x - m); v[j].y = __expf(v[j].y - m);
        v[j].z = __expf(v[j].z - m); v[j].w = __expf(v[j].w - m);
        sum += v[j].x + v[j].y + v[j].z + v[j].w;
    }
#pragma unroll
    for (int o = 16; o > 0; o >>= 1) sum += __shfl_xor_sync(0xFFFFFFFF, sum, o);
    if (lane == 0) red[wid] = sum;
    __syncthreads();
    sum = 0.0f;
#pragma unroll
    for (int w = 0; w < 8; w++) sum += red[w];
    float inv = 1.0f / sum;

    __half2* dst = (__half2*)(Pf + row * SEQ);
#pragma unroll
    for (int j = 0; j < 4; j++) {
        int e = (tid + j * 256) * 2;
        dst[e]     = __floats2half2_rn(v[j].x * inv, v[j].y * inv);
        dst[e + 1] = __floats2half2_rn(v[j].z * inv, v[j].w * inv);
    }
}

// ---------------- host ----------------
extern "C" void kernel_launch(void* const* d_in, const int* in_sizes, int n_in,
                              void* d_out, int out_size)
{
    const float* x  = (const float*)d_in[0];
    const float* Wq = (const float*)d_in[1];
    const float* Wk = (const float*)d_in[2];
    const float* Wv = (const float*)d_in[3];
    float* out = (float*)d_out;

    __half *xf, *Wqt, *Wkt, *Wvt, *Qf, *Kf, *Vtf, *Pf;
    float* S;
    cudaGetSymbolAddress((void**)&xf, g_xf);
    cudaGetSymbolAddress((void**)&Wqt, g_Wqt);
    cudaGetSymbolAddress((void**)&Wkt, g_Wkt);
    cudaGetSymbolAddress((void**)&Wvt, g_Wvt);
    cudaGetSymbolAddress((void**)&Qf, g_Qf);
    cudaGetSymbolAddress((void**)&Kf, g_Kf);
    cudaGetSymbolAddress((void**)&Vtf, g_Vtf);
    cudaGetSymbolAddress((void**)&Pf, g_Pf);
    cudaGetSymbolAddress((void**)&S, g_S);

    cudaFuncSetAttribute(gemm_f16<0>, cudaFuncAttributeMaxDynamicSharedMemorySize, GSMEM_F16);
    cudaFuncSetAttribute(gemm_f16<1>, cudaFuncAttributeMaxDynamicSharedMemorySize, GSMEM_F16);

    // 1) convert x -> fp16; W -> W^T fp16
    convert_f16<<<(MTOT*DM/4 + 255)/256, 256>>>(x, xf, MTOT*DM/4);
    wtrans_f16<<<DM*DM/256, 256>>>(Wq, Wqt);
    wtrans_f16<<<DM*DM/256, 256>>>(Wk, Wkt);
    wtrans_f16<<<DM*DM/256, 256>>>(Wv, Wvt);

    // 2) Q = x@Wq, K = x@Wk  (single-term fp16, fp16 out)
    {
        dim3 g(DM/128, MTOT/128, 1);
        gemm_f16<1><<<g, 256, GSMEM_F16>>>(xf, Wqt, nullptr, Qf,
                                           DM, DM, DM, DM, 0, 0, 0, 1.0f);
        gemm_f16<1><<<g, 256, GSMEM_F16>>>(xf, Wkt, nullptr, Kf,
                                           DM, DM, DM, DM, 0, 0, 0, 1.0f);
    }
    // 3) V^T = Wv^T @ x^T  -> fp16 [512, 8192]
    {
        dim3 g(MTOT/128, DM/128, 1);
        gemm_f16<1><<<g, 256, GSMEM_F16>>>(Wvt, xf, nullptr, Vtf,
                                           DM, DM, DM, MTOT, 0, 0, 0, 1.0f);
    }
    // 4) scores = (Qf @ Kf^T) / sqrt(512)
    {
        dim3 g(SEQ/128, SEQ/128, BATCH);
        gemm_f16<0><<<g, 256, GSMEM_F16>>>(Qf, Kf, S, nullptr,
                                           DM, DM, DM, SEQ,
                                           (long long)SEQ*DM, (long long)SEQ*DM,
                                           (long long)SEQ*SEQ, 0.044194173824159216f);
    }
    // 5) softmax -> fp16 P
    softmax_f16<<<BATCH*SEQ, 256>>>(S, Pf);

    // 6) out = Pf @ Vtf^T
    {
        dim3 g(DM/128, SEQ/128, BATCH);
        gemm_f16<0><<<g, 256, GSMEM_F16>>>(Pf, Vtf, out, nullptr,
                                           SEQ, SEQ, MTOT, DM,
                                           (long long)SEQ*SEQ, (long long)SEQ,
                                           (long long)SEQ*DM, 1.0f);
    }
}

// round 15
// speedup vs baseline: 5.6761x; 1.0580x over previous
#include <cuda_runtime.h>
#include <cuda_fp16.h>
#include <cstdint>
#include <math.h>

#define BATCH 2
#define SEQ   4096
#define DM    512
#define MTOT  (BATCH*SEQ)            // 8192

// ---------------- device scratch (no allocs allowed) ----------------
__device__ __half g_xf[MTOT*DM];                                 // x fp16
__device__ __half g_Wqt[DM*DM], g_Wkt[DM*DM], g_Wvt[DM*DM];      // W^T fp16
__device__ __half g_Qf[MTOT*DM];                                 // Q fp16
__device__ __half g_Kf[MTOT*DM];                                 // K fp16
__device__ __half g_Vtf[DM*MTOT];                                // V^T fp16 [512, 8192]
__device__ __half g_Ef[(long long)BATCH*SEQ*SEQ];                // exp(scores) fp16
__device__ float  g_partials[32*MTOT];                           // row-sum partials [j][row]
__device__ float  g_invs[MTOT];                                  // 1/rowsum

// ---------------- PTX helpers ----------------
__device__ __forceinline__ uint32_t smem_u32(const void* p) {
    uint32_t a;
    asm("{ .reg .u64 t; cvta.to.shared.u64 t, %1; cvt.u32.u64 %0, t; }" : "=r"(a) : "l"(p));
    return a;
}
__device__ __forceinline__ void cpasync16(uint32_t dst, const void* src) {
    asm volatile("cp.async.cg.shared.global [%0], [%1], 16;" :: "r"(dst), "l"(src));
}
__device__ __forceinline__ void cp_commit() {
    asm volatile("cp.async.commit_group;" ::: "memory");
}
template<int N>
__device__ __forceinline__ void cp_wait() {
    asm volatile("cp.async.wait_group %0;" :: "n"(N) : "memory");
}
__device__ __forceinline__ void ldmx4(uint32_t* r, uint32_t addr) {
    asm volatile("ldmatrix.sync.aligned.m8n8.x4.shared.b16 {%0,%1,%2,%3}, [%4];"
                 : "=r"(r[0]), "=r"(r[1]), "=r"(r[2]), "=r"(r[3]) : "r"(addr));
}
__device__ __forceinline__ void mma16816h(float* c, const uint32_t* a, const uint32_t* b) {
    asm volatile(
        "mma.sync.aligned.m16n8k16.row.col.f32.f16.f16.f32 "
        "{%0,%1,%2,%3}, {%4,%5,%6,%7}, {%8,%9}, {%0,%1,%2,%3};"
        : "+f"(c[0]), "+f"(c[1]), "+f"(c[2]), "+f"(c[3])
        : "r"(a[0]), "r"(a[1]), "r"(a[2]), "r"(a[3]), "r"(b[0]), "r"(b[1]));
}

// ---------------- tiling constants ----------------
#define ROWB    80                 // padded row stride in bytes (40 halves)
#define MAT_B   (128*ROWB)         // 10240 B per matrix tile
#define F16_STAGE_B (2*MAT_B)      // 20480 B per stage
#define F16_NSTAGE  3
#define GSMEM_F16   (F16_NSTAGE*F16_STAGE_B + 128)

// ---------------- single-term fp16 GEMM ----------------
// C = A @ B^T ; A[M,K], B[N,K] fp16 row-major, fp32 accumulate.
// EPI==1: fp16 out (Cf)                         [projections]
// EPI==2: fp32 out scaled by invs[bz*SEQ+row]   [P@V]
// EPI==3: Cf = fp16 exp(alpha*acc); row-sum partials -> Part[bx*MTOT + bz*SEQ + r]
template<int EPI>
__global__ __launch_bounds__(256, 2) void gemm_f16(
    const __half* __restrict__ A, const __half* __restrict__ B,
    float* __restrict__ C, __half* __restrict__ Cf,
    const float* __restrict__ invs, float* __restrict__ Part,
    int K, int lda, int ldb, int ldc,
    long long sA, long long sB, long long sC, float alpha)
{
    extern __shared__ char dsm[];
    const uint32_t smem0 = (smem_u32(dsm) + 127) & ~127u;

    const int tid = threadIdx.x;
    const int lane = tid & 31;
    const int wid = tid >> 5;
    const int warpM = wid & 1;
    const int warpN = wid >> 1;
    const int g = lane >> 2;
    const int tig = lane & 3;

    const long long bz = blockIdx.z;
    A += bz * sA;
    B += bz * sB;
    const int rowBase = blockIdx.y * 128;
    const int colBase = blockIdx.x * 128;

    const int q = tid & 3;
    const int rbase = tid >> 2;

    const __half* srcA = A + (long long)rowBase * lda + q * 8;
    const __half* srcB = B + (long long)colBase * ldb + q * 8;

    auto load_stage = [&](int buf, int k0) {
        const uint32_t stg = smem0 + buf * F16_STAGE_B;
#pragma unroll
        for (int i = 0; i < 4; i++) {
            const int mat = i >> 1;
            const int r = rbase + (i & 1) * 64;
            const uint32_t dst = stg + mat * MAT_B + r * ROWB + q * 16;
            const __half* src = (mat == 0) ? srcA + (long long)r * lda + k0
                                           : srcB + (long long)r * ldb + k0;
            cpasync16(dst, src);
        }
        cp_commit();
    };

    const int tile = lane >> 3, trow = lane & 7;
    const uint32_t aoff = (uint32_t)((warpM * 64 + ((tile & 1) << 3) + trow) * ROWB
                                     + ((tile >> 1) << 4));
    const uint32_t boff = (uint32_t)((warpN * 32 + ((tile >> 1) << 3) + trow) * ROWB
                                     + ((tile & 1) << 4));

    float acc[4][4][4];
#pragma unroll
    for (int mt = 0; mt < 4; mt++)
#pragma unroll
        for (int nt = 0; nt < 4; nt++)
#pragma unroll
            for (int v = 0; v < 4; v++) acc[mt][nt][v] = 0.0f;

    const int NC = K >> 5;
    load_stage(0, 0);
    if (NC > 1) load_stage(1, 32);

    for (int it = 0; it < NC; it++) {
        if (it + 2 < NC) { load_stage((it + 2) % F16_NSTAGE, (it + 2) << 5); cp_wait<2>(); }
        else if (it + 1 < NC) { cp_wait<1>(); }
        else { cp_wait<0>(); }
        __syncthreads();

        const uint32_t stg = smem0 + (it % F16_NSTAGE) * F16_STAGE_B;
        const uint32_t sA_ = stg;
        const uint32_t sB_ = stg + MAT_B;

#pragma unroll
        for (int ks = 0; ks < 2; ks++) {
            const uint32_t kb = ks * 32;
            uint32_t af[4][4], bf[4][2];
#pragma unroll
            for (int mt = 0; mt < 4; mt++)
                ldmx4(af[mt], sA_ + aoff + mt * (16 * ROWB) + kb);
#pragma unroll
            for (int p = 0; p < 2; p++)
                ldmx4(&bf[2 * p][0], sB_ + boff + p * (16 * ROWB) + kb);
#pragma unroll
            for (int mt = 0; mt < 4; mt++)
#pragma unroll
                for (int nt = 0; nt < 4; nt++)
                    mma16816h(acc[mt][nt], af[mt], bf[nt]);
        }
        __syncthreads();
    }

    // ---- epilogues ----
    if (EPI == 1) {
#pragma unroll
        for (int mt = 0; mt < 4; mt++)
#pragma unroll
            for (int nt = 0; nt < 4; nt++) {
                const int row = rowBase + warpM * 64 + mt * 16 + g;
                const int col = colBase + warpN * 32 + nt * 8 + tig * 2;
                long long o0 = (long long)row * ldc + col;
                long long o1 = (long long)(row + 8) * ldc + col;
                *(__half2*)(Cf + o0) = __floats2half2_rn(acc[mt][nt][0], acc[mt][nt][1]);
                *(__half2*)(Cf + o1) = __floats2half2_rn(acc[mt][nt][2], acc[mt][nt][3]);
            }
    } else if (EPI == 2) {
#pragma unroll
        for (int mt = 0; mt < 4; mt++)
#pragma unroll
            for (int nt = 0; nt < 4; nt++) {
                const int row = rowBase + warpM * 64 + mt * 16 + g;
                const int col = colBase + warpN * 32 + nt * 8 + tig * 2;
                const float s0 = invs[bz * SEQ + row];
                const float s1 = invs[bz * SEQ + row + 8];
                float2 v0 = make_float2(acc[mt][nt][0] * s0, acc[mt][nt][1] * s0);
                float2 v1 = make_float2(acc[mt][nt][2] * s1, acc[mt][nt][3] * s1);
                float* base = C + bz * sC;
                *(float2*)(base + (long long)row * ldc + col) = v0;
                *(float2*)(base + (long long)(row + 8) * ldc + col) = v1;
            }
    } else { // EPI == 3: exp epilogue + row-sum partials
        // exp in place
#pragma unroll
        for (int mt = 0; mt < 4; mt++)
#pragma unroll
            for (int nt = 0; nt < 4; nt++)
#pragma unroll
                for (int v = 0; v < 4; v++)
                    acc[mt][nt][v] = __expf(alpha * acc[mt][nt][v]);

        // write E (fp16)
#pragma unroll
        for (int mt = 0; mt < 4; mt++)
#pragma unroll
            for (int nt = 0; nt < 4; nt++) {
                const int row = rowBase + warpM * 64 + mt * 16 + g;
                const int col = colBase + warpN * 32 + nt * 8 + tig * 2;
                long long o0 = bz * sC + (long long)row * ldc + col;
                long long o1 = bz * sC + (long long)(row + 8) * ldc + col;
                *(__half2*)(Cf + o0) = __floats2half2_rn(acc[mt][nt][0], acc[mt][nt][1]);
                *(__half2*)(Cf + o1) = __floats2half2_rn(acc[mt][nt][2], acc[mt][nt][3]);
            }

        // per-thread row partials -> smem [128 rows][16 slots] -> partials
        float* rowred = (float*)dsm;   // mainloop smem no longer needed
        const int slot = warpN * 4 + tig;
#pragma unroll
        for (int mt = 0; mt < 4; mt++) {
            float p0 = 0.0f, p1 = 0.0f;
#pragma unroll
            for (int nt = 0; nt < 4; nt++) {
                p0 += acc[mt][nt][0] + acc[mt][nt][1];
                p1 += acc[mt][nt][2] + acc[mt][nt][3];
            }
            const int r0 = warpM * 64 + mt * 16 + g;
            rowred[r0 * 16 + slot]       = p0;
            rowred[(r0 + 8) * 16 + slot] = p1;
        }
        __syncthreads();
        if (tid < 128) {
            float s = 0.0f;
#pragma unroll
            for (int j = 0; j < 16; j++) s += rowred[tid * 16 + j];
            Part[(long long)blockIdx.x * MTOT + bz * SEQ + rowBase + tid] = s;
        }
    }
}

// ---------------- row-sum finalize: invs[row] = 1 / sum_j partials[j][row] ----------------
__global__ __launch_bounds__(256) void sumrow(
    const float* __restrict__ Part, float* __restrict__ invs)
{
    int row = blockIdx.x * 256 + threadIdx.x;
    if (row >= MTOT) return;
    float s = 0.0f;
#pragma unroll
    for (int j = 0; j < 32; j++) s += Part[j * MTOT + row];
    invs[row] = 1.0f / s;
}

// ---------------- fp32 -> fp16 convert (x) ----------------
__global__ __launch_bounds__(256) void convert_f16(
    const float* __restrict__ x, __half* __restrict__ xf, int n4)
{
    int i = blockIdx.x * 256 + threadIdx.x;
    if (i >= n4) return;
    float4 v = ((const float4*)x)[i];
    ((__half2*)xf)[2*i]   = __floats2half2_rn(v.x, v.y);
    ((__half2*)xf)[2*i+1] = __floats2half2_rn(v.z, v.w);
}

// ---------------- transpose + fp16 convert, all three W in one launch ----------------
__global__ __launch_bounds__(256) void wtrans3_f16(
    const float* __restrict__ W0, const float* __restrict__ W1, const float* __restrict__ W2,
    __half* __restrict__ T0, __half* __restrict__ T1, __half* __restrict__ T2)
{
    int idx = blockIdx.x * 256 + threadIdx.x;   // over 512*512
    const float* W = (blockIdx.y == 0) ? W0 : (blockIdx.y == 1) ? W1 : W2;
    __half*      T = (blockIdx.y == 0) ? T0 : (blockIdx.y == 1) ? T1 : T2;
    int k = idx >> 9, n = idx & 511;
    T[n * 512 + k] = __float2half_rn(W[idx]);   // coalesced read, scattered write
}

// ---------------- host ----------------
extern "C" void kernel_launch(void* const* d_in, const int* in_sizes, int n_in,
                              void* d_out, int out_size)
{
    const float* x  = (const float*)d_in[0];
    const float* Wq = (const float*)d_in[1];
    const float* Wk = (const float*)d_in[2];
    const float* Wv = (const float*)d_in[3];
    float* out = (float*)d_out;

    __half *xf, *Wqt, *Wkt, *Wvt, *Qf, *Kf, *Vtf, *Ef;
    float *Part, *invs;
    cudaGetSymbolAddress((void**)&xf, g_xf);
    cudaGetSymbolAddress((void**)&Wqt, g_Wqt);
    cudaGetSymbolAddress((void**)&Wkt, g_Wkt);
    cudaGetSymbolAddress((void**)&Wvt, g_Wvt);
    cudaGetSymbolAddress((void**)&Qf, g_Qf);
    cudaGetSymbolAddress((void**)&Kf, g_Kf);
    cudaGetSymbolAddress((void**)&Vtf, g_Vtf);
    cudaGetSymbolAddress((void**)&Ef, g_Ef);
    cudaGetSymbolAddress((void**)&Part, g_partials);
    cudaGetSymbolAddress((void**)&invs, g_invs);

    cudaFuncSetAttribute(gemm_f16<1>, cudaFuncAttributeMaxDynamicSharedMemorySize, GSMEM_F16);
    cudaFuncSetAttribute(gemm_f16<2>, cudaFuncAttributeMaxDynamicSharedMemorySize, GSMEM_F16);
    cudaFuncSetAttribute(gemm_f16<3>, cudaFuncAttributeMaxDynamicSharedMemorySize, GSMEM_F16);

    // 1) converts
    convert_f16<<<(MTOT*DM/4 + 255)/256, 256>>>(x, xf, MTOT*DM/4);
    {
        dim3 g(DM*DM/256, 3, 1);
        wtrans3_f16<<<g, 256>>>(Wq, Wk, Wv, Wqt, Wkt, Wvt);
    }

    // 2) Q = x@Wq, K = x@Wk  (fp16 out)
    {
        dim3 g(DM/128, MTOT/128, 1);
        gemm_f16<1><<<g, 256, GSMEM_F16>>>(xf, Wqt, nullptr, Qf, nullptr, nullptr,
                                           DM, DM, DM, DM, 0, 0, 0, 1.0f);
        gemm_f16<1><<<g, 256, GSMEM_F16>>>(xf, Wkt, nullptr, Kf, nullptr, nullptr,
                                           DM, DM, DM, DM, 0, 0, 0, 1.0f);
    }
    // 3) V^T = Wv^T @ x^T  -> fp16 [512, 8192]
    {
        dim3 g(MTOT/128, DM/128, 1);
        gemm_f16<1><<<g, 256, GSMEM_F16>>>(Wvt, xf, nullptr, Vtf, nullptr, nullptr,
                                           DM, DM, DM, MTOT, 0, 0, 0, 1.0f);
    }
    // 4) E = exp(Q@K^T / sqrt(512)) fp16 + row-sum partials
    {
        dim3 g(SEQ/128, SEQ/128, BATCH);
        gemm_f16<3><<<g, 256, GSMEM_F16>>>(Qf, Kf, nullptr, Ef, nullptr, Part,
                                           DM, DM, DM, SEQ,
                                           (long long)SEQ*DM, (long long)SEQ*DM,
                                           (long long)SEQ*SEQ, 0.044194173824159216f);
    }
    // 5) inv row sums
    sumrow<<<(MTOT + 255)/256, 256>>>(Part, invs);

    // 6) out = (E @ V) * invs[row]
    {
        dim3 g(DM/128, SEQ/128, BATCH);
        gemm_f16<2><<<g, 256, GSMEM_F16>>>(Ef, Vtf, out, nullptr, invs, nullptr,
                                           SEQ, SEQ, MTOT, DM,
                                           (long long)SEQ*SEQ, (long long)SEQ,
                                           (long long)SEQ*DM, 1.0f);
    }
}